// round 12
// baseline (speedup 1.0000x reference)
#include <cuda_runtime.h>
#include <cuda_bf16.h>
#include <cstdint>
#include <math.h>

// Problem constants
#define BB 8
#define TT 4096
#define HH 512
#define MTOT (BB*TT)          // 32768 rows

// ---------------- scratch (static device globals; no allocation) -------------
__device__ __align__(16) float g_pe[(size_t)TT * HH];      // 8 MB
__device__ float  g_div[256];
__device__ double g_C[HH * 2];       // 8 * W_embed @ Wx
__device__ double g_d[TT * 2];       // 8 * (b_embed + pe[t]) @ Wx
__device__ int    g_mask[MTOT];
__device__ int    g_sel[MTOT];
__device__ int    g_lens[BB];
__device__ __align__(16) __nv_bfloat16 g_A1[(size_t)MTOT * HH];  // packed rows only
__device__ __align__(16) __nv_bfloat16 g_A2[(size_t)MTOT * HH];
__device__ __align__(16) __nv_bfloat16 g_A3[(size_t)MTOT * HH];
__device__ __align__(16) __nv_bfloat16 g_W1[HH * HH];            // transposed [n][k]
__device__ __align__(16) __nv_bfloat16 g_W2[HH * HH];
__device__ __align__(16) __nv_bfloat16 g_W3[HH * HH];

// ---------------- helpers ----------------------------------------------------
__device__ __forceinline__ uint32_t smem_to_u32(const void* p) {
    uint32_t a;
    asm("{ .reg .u64 t; cvta.to.shared.u64 t, %1; cvt.u32.u64 %0, t; }" : "=r"(a) : "l"(p));
    return a;
}
__device__ __forceinline__ void cpasync16(uint32_t sa, const void* g) {
    asm volatile("cp.async.cg.shared.global [%0], [%1], 16;" :: "r"(sa), "l"(g));
}
__device__ __forceinline__ void ldm_x4(uint32_t* r, uint32_t addr) {
    asm volatile("ldmatrix.sync.aligned.m8n8.x4.shared.b16 {%0,%1,%2,%3}, [%4];"
        : "=r"(r[0]), "=r"(r[1]), "=r"(r[2]), "=r"(r[3]) : "r"(addr));
}
__device__ __forceinline__ void mma16816(float* d, const uint32_t* a,
                                         uint32_t b0, uint32_t b1) {
    asm volatile("mma.sync.aligned.m16n8k16.row.col.f32.bf16.bf16.f32 "
        "{%0,%1,%2,%3}, {%4,%5,%6,%7}, {%8,%9}, {%0,%1,%2,%3};"
        : "+f"(d[0]), "+f"(d[1]), "+f"(d[2]), "+f"(d[3])
        : "r"(a[0]), "r"(a[1]), "r"(a[2]), "r"(a[3]), "r"(b0), "r"(b1));
}

// ---------------- threefry2x32 (Random123 / JAX-compatible) ------------------
__host__ __device__ __forceinline__
void threefry2x32(uint32_t k0, uint32_t k1, uint32_t x0, uint32_t x1,
                  uint32_t& o0, uint32_t& o1)
{
    uint32_t ks2 = k0 ^ k1 ^ 0x1BD11BDAu;
    x0 += k0; x1 += k1;
#define RND(r) { x0 += x1; x1 = (x1 << r) | (x1 >> (32 - r)); x1 ^= x0; }
    RND(13) RND(15) RND(26) RND(6)
    x0 += k1; x1 += ks2 + 1u;
    RND(17) RND(29) RND(16) RND(24)
    x0 += ks2; x1 += k0 + 2u;
    RND(13) RND(15) RND(26) RND(6)
    x0 += k0; x1 += k1 + 3u;
    RND(17) RND(29) RND(16) RND(24)
    x0 += k1; x1 += ks2 + 4u;
    RND(13) RND(15) RND(26) RND(6)
    x0 += ks2; x1 += k0 + 5u;
#undef RND
    o0 = x0; o1 = x1;
}

// gumbel draw, jax_threefry_partitionable=True: bits = o0 ^ o1 of (key, (0, idx))
__device__ __forceinline__
float gumbel_at(uint32_t k0, uint32_t k1, uint32_t idx)
{
    uint32_t o0, o1;
    threefry2x32(k0, k1, 0u, idx, o0, o1);
    uint32_t bits = o0 ^ o1;
    uint32_t fb = (bits >> 9) | 0x3f800000u;
    float f = __uint_as_float(fb) - 1.0f;
    float u = fmaxf(f, 1.17549435e-38f);
    float l1 = (float)log((double)u);
    return -(float)log((double)(-l1));
}

// ---------------- K: inv-freq table ------------------------------------------
__global__ void div_kernel()
{
    int j = threadIdx.x;
    double c = -log(10000.0) / 512.0;
    float arg = (float)(2 * j) * (float)c;
    g_div[j] = (float)exp((double)arg);
}

// ---------------- K: PE table [4096, 512] ------------------------------------
__global__ __launch_bounds__(256) void pe_kernel()
{
    int t = blockIdx.x;
    float tf = (float)t;
    for (int n = threadIdx.x; n < 512; n += 256) {
        float ang = tf * g_div[n >> 1];
        g_pe[(size_t)t * 512 + n] = (n & 1) ? cosf(ang) : sinf(ang);
    }
}

// ---------------- K: zero the output -----------------------------------------
__global__ __launch_bounds__(256) void zero_kernel(float4* __restrict__ out)
{
    out[(size_t)blockIdx.x * 256 + threadIdx.x] = make_float4(0.f, 0.f, 0.f, 0.f);
}

// ---------------- K: C = 8 * W_embed @ Wx  (fp64) ----------------------------
__global__ __launch_bounds__(256) void cproj_kernel(const float* __restrict__ W,
                                                    const float* __restrict__ Wx)
{
    int idx = blockIdx.x * 256 + threadIdx.x;   // 0..1023
    int k = idx >> 1, i = idx & 1;
    double s = 0.0;
    for (int j = 0; j < 512; j++)
        s += (double)W[(size_t)k * 512 + j] * (double)Wx[j * 2 + i];
    g_C[idx] = 8.0 * s;
}

// ---------------- K: d[t] = 8 * (b_embed + pe[t]) @ Wx  (fp64) ---------------
__global__ __launch_bounds__(32) void dtab_kernel(const float* __restrict__ bias,
                                                  const float* __restrict__ Wx)
{
    int t = blockIdx.x, lane = threadIdx.x;
    double s0 = 0.0, s1 = 0.0;
    for (int j = lane; j < 512; j += 32) {
        double e = (double)bias[j] + (double)g_pe[(size_t)t * 512 + j];
        s0 += e * (double)Wx[2 * j];
        s1 += e * (double)Wx[2 * j + 1];
    }
#pragma unroll
    for (int off = 16; off; off >>= 1) {
        s0 += __shfl_xor_sync(0xffffffffu, s0, off);
        s1 += __shfl_xor_sync(0xffffffffu, s1, off);
    }
    if (lane == 0) { g_d[t * 2] = 8.0 * s0; g_d[t * 2 + 1] = 8.0 * s1; }
}

// ---------------- K: split + transpose W into bf16 [n][k] --------------------
__global__ void splitW_kernel(const float* __restrict__ W)
{
    __shared__ float ts[32][33];
    int kt = blockIdx.y * 32, nt = blockIdx.x * 32;
    int tx = threadIdx.x, ty = threadIdx.y;   // 32 x 8
    for (int i = ty; i < 32; i += 8)
        ts[i][tx] = W[(size_t)(kt + i) * 512 + nt + tx];
    __syncthreads();
    for (int i = ty; i < 32; i += 8) {
        float x = ts[tx][i];   // = W[kt+tx][nt+i]
        __nv_bfloat16 h1 = __float2bfloat16(x);
        float r = x - __bfloat162float(h1);
        __nv_bfloat16 h2 = __float2bfloat16(r);
        float r2 = r - __bfloat162float(h2);
        __nv_bfloat16 h3 = __float2bfloat16(r2);
        size_t o = (size_t)(nt + i) * 512 + kt + tx;
        g_W1[o] = h1; g_W2[o] = h2; g_W3[o] = h3;
    }
}

// ---------------- K: filter — logits from data directly, gumbel-max ----------
// logit_i(token m=b*4096+t) = data_m . C_i + d[t][i] + (v_f @ Wv)_i + bf_i
__global__ __launch_bounds__(256)
void filter_kernel(const float* __restrict__ data,
                   const float* __restrict__ Wv,   // [512,2]
                   const float* __restrict__ bf,   // [2]
                   const float* __restrict__ v0,   // [8,512]
                   const float* __restrict__ v1,   // [8,512]
                   uint32_t ka0, uint32_t ka1, uint32_t kb0, uint32_t kb1)
{
    const int tid = threadIdx.x;
    const int b = blockIdx.x >> 9;            // 512 blocks per batch row
    __shared__ double sC[1024];
    __shared__ double cb[2][2];

    for (int k = tid; k < 1024; k += 256) sC[k] = g_C[k];

    if (tid < 32) {
        double s00 = 0, s01 = 0, s10 = 0, s11 = 0;
        for (int k = tid; k < 512; k += 32) {
            double w0 = Wv[2 * k], w1 = Wv[2 * k + 1];
            double a = v0[b * 512 + k], c = v1[b * 512 + k];
            s00 += a * w0; s01 += a * w1;
            s10 += c * w0; s11 += c * w1;
        }
#pragma unroll
        for (int off = 16; off; off >>= 1) {
            s00 += __shfl_xor_sync(0xffffffffu, s00, off);
            s01 += __shfl_xor_sync(0xffffffffu, s01, off);
            s10 += __shfl_xor_sync(0xffffffffu, s10, off);
            s11 += __shfl_xor_sync(0xffffffffu, s11, off);
        }
        if (tid == 0) {
            cb[0][0] = s00 + (double)bf[0]; cb[0][1] = s01 + (double)bf[1];
            cb[1][0] = s10 + (double)bf[0]; cb[1][1] = s11 + (double)bf[1];
        }
    }
    __syncthreads();

    const int warp = tid >> 5, lane = tid & 31;
    const int m = blockIdx.x * 8 + warp;      // global token row
    const int tloc = m & 4095;
    const float4* dp = (const float4*)(data + (size_t)m * 512);

    double d0 = 0.0, d1 = 0.0;
#pragma unroll
    for (int r = 0; r < 4; r++) {
        int j4 = lane + 32 * r;
        float4 x = dp[j4];
        int j = j4 * 4;
        d0 += (double)x.x * sC[(j + 0) * 2] + (double)x.y * sC[(j + 1) * 2]
            + (double)x.z * sC[(j + 2) * 2] + (double)x.w * sC[(j + 3) * 2];
        d1 += (double)x.x * sC[(j + 0) * 2 + 1] + (double)x.y * sC[(j + 1) * 2 + 1]
            + (double)x.z * sC[(j + 2) * 2 + 1] + (double)x.w * sC[(j + 3) * 2 + 1];
    }
#pragma unroll
    for (int off = 16; off; off >>= 1) {
        d0 += __shfl_xor_sync(0xffffffffu, d0, off);
        d1 += __shfl_xor_sync(0xffffffffu, d1, off);
    }
    if (lane == 0) {
        double sd0 = g_d[tloc * 2], sd1 = g_d[tloc * 2 + 1];
        uint32_t base = (uint32_t)(b * 8192 + 2 * tloc);
        float g00 = gumbel_at(ka0, ka1, base);
        float g01 = gumbel_at(ka0, ka1, base + 1u);
        float g10 = gumbel_at(kb0, kb1, base);
        float g11 = gumbel_at(kb0, kb1, base + 1u);
        float l00 = (float)(d0 + sd0 + cb[0][0]), l01 = (float)(d1 + sd1 + cb[0][1]);
        float l10 = (float)(d0 + sd0 + cb[1][0]), l11 = (float)(d1 + sd1 + cb[1][1]);
        int f0 = ((l00 + g00) >= (l01 + g01));
        int f1 = ((l10 + g10) >= (l11 + g11));
        g_mask[m] = f0 & f1;
    }
}

// ---------------- K: per-row stable exclusive scan --> sel indices -----------
__global__ __launch_bounds__(256)
void scan_kernel()
{
    const int b = blockIdx.x;
    const int tid = threadIdx.x;
    const int base = tid * 16;

    int m[16];
    int cnt = 0;
#pragma unroll
    for (int q = 0; q < 16; q++) {
        m[q] = g_mask[b * 4096 + base + q];
        cnt += m[q];
    }

    const int lane = tid & 31, warp = tid >> 5;
    int v = cnt;
#pragma unroll
    for (int off = 1; off < 32; off <<= 1) {
        int n2 = __shfl_up_sync(0xffffffffu, v, off);
        if (lane >= off) v += n2;
    }
    __shared__ int wtot[8];
    if (lane == 31) wtot[warp] = v;
    __syncthreads();
    int woff = 0;
    for (int w = 0; w < warp; w++) woff += wtot[w];
    int excl = woff + v - cnt;

    int pos = excl;
#pragma unroll
    for (int q = 0; q < 16; q++) {
        if (m[q]) g_sel[b * 4096 + pos++] = base + q;
    }
    if (tid == 255) g_lens[b] = excl + cnt;
}

// ---------------- K: pack selected data rows -> bf16x3 splits ----------------
__global__ __launch_bounds__(256)
void packA_kernel(const float* __restrict__ data)
{
    const int tid = threadIdx.x;
    const int rl = tid >> 7;                 // 0..1 row within block
    const int c4 = tid & 127;                // float4 index in row
    const int p = blockIdx.x * 2 + rl;       // packed row 0..32767
    const int b = p >> 12, k = p & 4095;
    if (k >= g_lens[b]) return;
    const int t = g_sel[p];
    float4 v = ((const float4*)(data + ((size_t)(b << 12) + t) * 512))[c4];
    float x[4] = {v.x, v.y, v.z, v.w};
    __nv_bfloat16 h1[4], h2[4], h3[4];
#pragma unroll
    for (int i = 0; i < 4; i++) {
        h1[i] = __float2bfloat16(x[i]);
        float r = x[i] - __bfloat162float(h1[i]);
        h2[i] = __float2bfloat16(r);
        float r2 = r - __bfloat162float(h2[i]);
        h3[i] = __float2bfloat16(r2);
    }
    size_t o4 = (size_t)p * 128 + c4;
    uint2 u;
    __nv_bfloat162 pk;
#define PACK(dst, h) \
    pk = __halves2bfloat162((h)[0], (h)[1]); u.x = *(uint32_t*)&pk; \
    pk = __halves2bfloat162((h)[2], (h)[3]); u.y = *(uint32_t*)&pk; \
    ((uint2*)(dst))[o4] = u;
    PACK(g_A1, h1) PACK(g_A2, h2) PACK(g_A3, h3)
#undef PACK
}

// ---------------- K: mma.sync bf16x3 GEMM over packed rows -> out ------------
// CTA 128x128, 256 thr (8 warps, warp 32x64), K chunks of 32, double-buffered.
// SMEM rows padded to 40 bf16 (80B) -> conflict-free ldmatrix, 16B aligned.
#define ROWB 80
#define MATB (128 * ROWB)          // 10240 B per matrix
#define STAGEB (6 * MATB)          // 61440 B per stage (A1..3, W1..3)
#define GEMM_SMEM (2 * STAGEB)     // 122880 B

__global__ __launch_bounds__(256, 1)
void mma_gemm_kernel(const float* __restrict__ bias, float* __restrict__ out)
{
    const int n0 = blockIdx.x * 128;
    const int m0 = blockIdx.y * 128;
    const int len = g_lens[m0 >> 12];
    if ((m0 & 4095) >= len) return;          // whole m-block beyond packed length

    extern __shared__ char smem[];
    const uint32_t sb = smem_to_u32(smem);
    const int tid = threadIdx.x;
    const int lane = tid & 31;
    const int w = tid >> 5;
    const int wm = w & 3;          // 4 m-strips of 32
    const int wn = w >> 2;         // 2 n-strips of 64

    const __nv_bfloat16* gmat[6] = {g_A1, g_A2, g_A3, g_W1, g_W2, g_W3};

    auto issue_copy = [&](int ch, int st) {
        const int k0 = ch * 32;
#pragma unroll
        for (int it = 0; it < 12; it++) {
            int idx = tid + it * 256;           // 0..3071
            int mi = idx >> 9;                  // matrix 0..5
            int r  = (idx >> 2) & 127;          // row in tile
            int c  = idx & 3;                   // 16B chunk in row
            int grow = ((mi < 3) ? m0 : n0) + r;
            const __nv_bfloat16* gp = gmat[mi] + (size_t)grow * 512 + k0 + c * 8;
            cpasync16(sb + st * STAGEB + mi * MATB + r * ROWB + c * 16, gp);
        }
        asm volatile("cp.async.commit_group;" ::: "memory");
    };

    float facc[2][8][4];
#pragma unroll
    for (int a = 0; a < 2; a++)
#pragma unroll
        for (int b = 0; b < 8; b++)
#pragma unroll
            for (int c = 0; c < 4; c++) facc[a][b][c] = 0.f;

    issue_copy(0, 0);

    const int rsel = lane & 15;
    const int chalf = (lane >> 4) << 4;     // 0 or 16 bytes

    for (int ch = 0; ch < 16; ch++) {
        const int st = ch & 1;
        asm volatile("cp.async.wait_group 0;" ::: "memory");
        __syncthreads();
        if (ch < 15) issue_copy(ch + 1, st ^ 1);

        const uint32_t bst = sb + st * STAGEB;
#pragma unroll
        for (int ks = 0; ks < 2; ks++) {
            const int colb = ks * 32 + chalf;
            uint32_t fa[3][2][4], fb[3][4][4];
#pragma unroll
            for (int sp = 0; sp < 3; sp++) {
#pragma unroll
                for (int mt = 0; mt < 2; mt++)
                    ldm_x4(fa[sp][mt],
                           bst + sp * MATB + (wm * 32 + mt * 16 + rsel) * ROWB + colb);
#pragma unroll
                for (int ng = 0; ng < 4; ng++)
                    ldm_x4(fb[sp][ng],
                           bst + (3 + sp) * MATB + (wn * 64 + ng * 16 + rsel) * ROWB + colb);
            }
            const int pa[6] = {0, 0, 1, 1, 0, 2};
            const int pb[6] = {0, 1, 0, 1, 2, 0};
#pragma unroll
            for (int p = 0; p < 6; p++)
#pragma unroll
                for (int mt = 0; mt < 2; mt++)
#pragma unroll
                    for (int ng = 0; ng < 4; ng++) {
                        mma16816(facc[mt][ng * 2 + 0], fa[pa[p]][mt],
                                 fb[pb[p]][ng][0], fb[pb[p]][ng][2]);
                        mma16816(facc[mt][ng * 2 + 1], fa[pa[p]][mt],
                                 fb[pb[p]][ng][1], fb[pb[p]][ng][3]);
                    }
        }
        __syncthreads();
    }

    // epilogue: per packed row m -> token t = g_sel[m]; out[m] = (acc+b+pe[t])*8
    int rowm[4], rowt[4];
    bool rok[4];
#pragma unroll
    for (int q = 0; q < 4; q++) {
        int mt = q >> 1, hh = q & 1;
        int m = m0 + wm * 32 + mt * 16 + (lane >> 2) + hh * 8;
        int k = m & 4095;
        rowm[q] = m;
        rok[q] = (k < len);
        rowt[q] = rok[q] ? g_sel[m] : 0;
    }

#pragma unroll
    for (int mt = 0; mt < 2; mt++)
#pragma unroll
        for (int nt = 0; nt < 8; nt++) {
            int n = n0 + wn * 64 + nt * 8 + (lane & 3) * 2;
            float b0 = bias[n], b1 = bias[n + 1];
            {
                int q = mt * 2;
                if (rok[q]) {
                    const float* pe = g_pe + (size_t)rowt[q] * 512 + n;
                    float2 v;
                    v.x = (facc[mt][nt][0] + b0 + pe[0]) * 8.0f;
                    v.y = (facc[mt][nt][1] + b1 + pe[1]) * 8.0f;
                    *(float2*)(out + (size_t)rowm[q] * 512 + n) = v;
                }
            }
            {
                int q = mt * 2 + 1;
                if (rok[q]) {
                    const float* pe = g_pe + (size_t)rowt[q] * 512 + n;
                    float2 v;
                    v.x = (facc[mt][nt][2] + b0 + pe[0]) * 8.0f;
                    v.y = (facc[mt][nt][3] + b1 + pe[1]) * 8.0f;
                    *(float2*)(out + (size_t)rowm[q] * 512 + n) = v;
                }
            }
        }
}

// ---------------- launch ------------------------------------------------------
extern "C" void kernel_launch(void* const* d_in, const int* in_sizes, int n_in,
                              void* d_out, int out_size)
{
    const float* data    = (const float*)d_in[0];
    const float* v0      = (const float*)d_in[1];
    const float* v1      = (const float*)d_in[2];
    const float* W_embed = (const float*)d_in[3];
    const float* b_embed = (const float*)d_in[4];
    const float* Wx      = (const float*)d_in[5];
    const float* Wv      = (const float*)d_in[6];
    const float* b_f     = (const float*)d_in[7];
    float* out = (float*)d_out;

    uint32_t ka0, ka1, kb0, kb1;
    threefry2x32(0u, 42u, 0u, 0u, ka0, ka1);
    threefry2x32(0u, 42u, 0u, 1u, kb0, kb1);

    cudaFuncSetAttribute(mma_gemm_kernel,
                         cudaFuncAttributeMaxDynamicSharedMemorySize, GEMM_SMEM);

    zero_kernel<<<16384, 256>>>((float4*)out);
    div_kernel<<<1, 256>>>();
    pe_kernel<<<4096, 256>>>();
    splitW_kernel<<<dim3(16, 16), dim3(32, 8)>>>(W_embed);
    cproj_kernel<<<4, 256>>>(W_embed, Wx);
    dtab_kernel<<<4096, 32>>>(b_embed, Wx);
    filter_kernel<<<4096, 256>>>(data, Wv, b_f, v0, v1, ka0, ka1, kb0, kb1);
    scan_kernel<<<8, 256>>>();
    packA_kernel<<<16384, 256>>>(data);
    mma_gemm_kernel<<<dim3(4, 256), 256, GEMM_SMEM>>>(b_embed, out);
}

// round 13
// speedup vs baseline: 1.5091x; 1.5091x over previous
#include <cuda_runtime.h>
#include <cuda_bf16.h>
#include <cstdint>
#include <math.h>

// Problem constants
#define BB 8
#define TT 4096
#define HH 512
#define MTOT (BB*TT)          // 32768 rows

// ---------------- scratch (static device globals; no allocation) -------------
__device__ __align__(16) float g_pe[(size_t)TT * HH];      // 8 MB
__device__ float  g_div[256];
__device__ float  g_C[HH * 2];       // 8 * W_embed @ Wx  (fp32, Kahan-computed)
__device__ double g_d[TT * 2];       // 8 * (b_embed + pe[t]) @ Wx
__device__ int    g_mask[MTOT];
__device__ int    g_sel[MTOT];
__device__ int    g_lens[BB];
__device__ __align__(16) __nv_bfloat16 g_A1[(size_t)MTOT * HH];  // packed rows only
__device__ __align__(16) __nv_bfloat16 g_A2[(size_t)MTOT * HH];
__device__ __align__(16) __nv_bfloat16 g_W1[HH * HH];            // transposed [n][k]
__device__ __align__(16) __nv_bfloat16 g_W2[HH * HH];

// ---------------- helpers ----------------------------------------------------
__device__ __forceinline__ uint32_t smem_to_u32(const void* p) {
    uint32_t a;
    asm("{ .reg .u64 t; cvta.to.shared.u64 t, %1; cvt.u32.u64 %0, t; }" : "=r"(a) : "l"(p));
    return a;
}
__device__ __forceinline__ void cpasync16(uint32_t sa, const void* g) {
    asm volatile("cp.async.cg.shared.global [%0], [%1], 16;" :: "r"(sa), "l"(g));
}
__device__ __forceinline__ void ldm_x4(uint32_t* r, uint32_t addr) {
    asm volatile("ldmatrix.sync.aligned.m8n8.x4.shared.b16 {%0,%1,%2,%3}, [%4];"
        : "=r"(r[0]), "=r"(r[1]), "=r"(r[2]), "=r"(r[3]) : "r"(addr));
}
__device__ __forceinline__ void mma16816(float* d, const uint32_t* a,
                                         uint32_t b0, uint32_t b1) {
    asm volatile("mma.sync.aligned.m16n8k16.row.col.f32.bf16.bf16.f32 "
        "{%0,%1,%2,%3}, {%4,%5,%6,%7}, {%8,%9}, {%0,%1,%2,%3};"
        : "+f"(d[0]), "+f"(d[1]), "+f"(d[2]), "+f"(d[3])
        : "r"(a[0]), "r"(a[1]), "r"(a[2]), "r"(a[3]), "r"(b0), "r"(b1));
}

// ---------------- threefry2x32 (Random123 / JAX-compatible) ------------------
__host__ __device__ __forceinline__
void threefry2x32(uint32_t k0, uint32_t k1, uint32_t x0, uint32_t x1,
                  uint32_t& o0, uint32_t& o1)
{
    uint32_t ks2 = k0 ^ k1 ^ 0x1BD11BDAu;
    x0 += k0; x1 += k1;
#define RND(r) { x0 += x1; x1 = (x1 << r) | (x1 >> (32 - r)); x1 ^= x0; }
    RND(13) RND(15) RND(26) RND(6)
    x0 += k1; x1 += ks2 + 1u;
    RND(17) RND(29) RND(16) RND(24)
    x0 += ks2; x1 += k0 + 2u;
    RND(13) RND(15) RND(26) RND(6)
    x0 += k0; x1 += k1 + 3u;
    RND(17) RND(29) RND(16) RND(24)
    x0 += k1; x1 += ks2 + 4u;
    RND(13) RND(15) RND(26) RND(6)
    x0 += ks2; x1 += k0 + 5u;
#undef RND
    o0 = x0; o1 = x1;
}

// gumbel draw, jax_threefry_partitionable=True: bits = o0 ^ o1 of (key, (0, idx))
__device__ __forceinline__
float gumbel_at(uint32_t k0, uint32_t k1, uint32_t idx)
{
    uint32_t o0, o1;
    threefry2x32(k0, k1, 0u, idx, o0, o1);
    uint32_t bits = o0 ^ o1;
    uint32_t fb = (bits >> 9) | 0x3f800000u;
    float f = __uint_as_float(fb) - 1.0f;
    float u = fmaxf(f, 1.17549435e-38f);
    float l1 = (float)log((double)u);
    return -(float)log((double)(-l1));
}

// ---------------- K: inv-freq table ------------------------------------------
__global__ void div_kernel()
{
    int j = threadIdx.x;
    double c = -log(10000.0) / 512.0;
    float arg = (float)(2 * j) * (float)c;
    g_div[j] = (float)exp((double)arg);
}

// ---------------- K: PE table [4096, 512] ------------------------------------
__global__ __launch_bounds__(256) void pe_kernel()
{
    int t = blockIdx.x;
    float tf = (float)t;
    for (int n = threadIdx.x; n < 512; n += 256) {
        float ang = tf * g_div[n >> 1];
        g_pe[(size_t)t * 512 + n] = (n & 1) ? cosf(ang) : sinf(ang);
    }
}

// ---------------- K: zero the output -----------------------------------------
__global__ __launch_bounds__(256) void zero_kernel(float4* __restrict__ out)
{
    out[(size_t)blockIdx.x * 256 + threadIdx.x] = make_float4(0.f, 0.f, 0.f, 0.f);
}

// ---------------- K: C = 8 * W_embed @ Wx  (Kahan fp32) ----------------------
__global__ __launch_bounds__(256) void cproj_kernel(const float* __restrict__ W,
                                                    const float* __restrict__ Wx)
{
    int idx = blockIdx.x * 256 + threadIdx.x;   // 0..1023
    int k = idx >> 1, i = idx & 1;
    float s = 0.f, c = 0.f;
    for (int j = 0; j < 512; j++) {
        float p = W[(size_t)k * 512 + j] * Wx[j * 2 + i];
        float y = p - c, t = s + y; c = (t - s) - y; s = t;
    }
    g_C[idx] = 8.0f * (s + c);
}

// ---------------- K: d[t] = 8 * (b_embed + pe[t]) @ Wx  (Kahan fp32) ---------
__global__ __launch_bounds__(32) void dtab_kernel(const float* __restrict__ bias,
                                                  const float* __restrict__ Wx)
{
    int t = blockIdx.x, lane = threadIdx.x;
    float s0 = 0.f, c0 = 0.f, s1 = 0.f, c1 = 0.f;
    for (int j = lane; j < 512; j += 32) {
        float e = bias[j] + g_pe[(size_t)t * 512 + j];
        float p0 = e * Wx[2 * j];
        float p1 = e * Wx[2 * j + 1];
        float y0 = p0 - c0, t0 = s0 + y0; c0 = (t0 - s0) - y0; s0 = t0;
        float y1 = p1 - c1, t1 = s1 + y1; c1 = (t1 - s1) - y1; s1 = t1;
    }
    s0 += c0; s1 += c1;
#pragma unroll
    for (int off = 16; off; off >>= 1) {
        s0 += __shfl_xor_sync(0xffffffffu, s0, off);
        s1 += __shfl_xor_sync(0xffffffffu, s1, off);
    }
    if (lane == 0) { g_d[t * 2] = 8.0 * (double)s0; g_d[t * 2 + 1] = 8.0 * (double)s1; }
}

// ---------------- K: split + transpose W into bf16x2 [n][k] ------------------
__global__ void splitW_kernel(const float* __restrict__ W)
{
    __shared__ float ts[32][33];
    int kt = blockIdx.y * 32, nt = blockIdx.x * 32;
    int tx = threadIdx.x, ty = threadIdx.y;   // 32 x 8
    for (int i = ty; i < 32; i += 8)
        ts[i][tx] = W[(size_t)(kt + i) * 512 + nt + tx];
    __syncthreads();
    for (int i = ty; i < 32; i += 8) {
        float x = ts[tx][i];   // = W[kt+tx][nt+i]
        __nv_bfloat16 h1 = __float2bfloat16(x);
        float r = x - __bfloat162float(h1);
        __nv_bfloat16 h2 = __float2bfloat16(r);
        size_t o = (size_t)(nt + i) * 512 + kt + tx;
        g_W1[o] = h1; g_W2[o] = h2;
    }
}

// ---------------- K: filter — logits from data directly, gumbel-max ----------
// logit_i(token m=b*4096+t) = data_m . C_i + d[t][i] + (v_f @ Wv)_i + bf_i
__global__ __launch_bounds__(256)
void filter_kernel(const float* __restrict__ data,
                   const float* __restrict__ Wv,   // [512,2]
                   const float* __restrict__ bf,   // [2]
                   const float* __restrict__ v0,   // [8,512]
                   const float* __restrict__ v1,   // [8,512]
                   uint32_t ka0, uint32_t ka1, uint32_t kb0, uint32_t kb1)
{
    const int tid = threadIdx.x;
    const int b = blockIdx.x >> 9;            // 512 blocks per batch row
    __shared__ float sC[1024];
    __shared__ double cb[2][2];

    for (int k = tid; k < 1024; k += 256) sC[k] = g_C[k];

    if (tid < 32) {
        // v @ Wv in Kahan fp32 (small: 2x512 per batch)
        float s00 = 0, e00 = 0, s01 = 0, e01 = 0, s10 = 0, e10 = 0, s11 = 0, e11 = 0;
        for (int k = tid; k < 512; k += 32) {
            float w0 = Wv[2 * k], w1 = Wv[2 * k + 1];
            float a = v0[b * 512 + k], c = v1[b * 512 + k];
#define KA(s, e, p) { float y = (p) - e, t = s + y; e = (t - s) - y; s = t; }
            KA(s00, e00, a * w0) KA(s01, e01, a * w1)
            KA(s10, e10, c * w0) KA(s11, e11, c * w1)
#undef KA
        }
        s00 += e00; s01 += e01; s10 += e10; s11 += e11;
#pragma unroll
        for (int off = 16; off; off >>= 1) {
            s00 += __shfl_xor_sync(0xffffffffu, s00, off);
            s01 += __shfl_xor_sync(0xffffffffu, s01, off);
            s10 += __shfl_xor_sync(0xffffffffu, s10, off);
            s11 += __shfl_xor_sync(0xffffffffu, s11, off);
        }
        if (tid == 0) {
            cb[0][0] = (double)s00 + (double)bf[0]; cb[0][1] = (double)s01 + (double)bf[1];
            cb[1][0] = (double)s10 + (double)bf[0]; cb[1][1] = (double)s11 + (double)bf[1];
        }
    }
    __syncthreads();

    const int warp = tid >> 5, lane = tid & 31;
    const int m = blockIdx.x * 8 + warp;      // global token row
    const int tloc = m & 4095;
    const float4* dp = (const float4*)(data + (size_t)m * 512);

    // Kahan fp32 dot (proven mask-exact in R8)
    float d0 = 0.f, c0 = 0.f, d1 = 0.f, c1 = 0.f;
#pragma unroll
    for (int r = 0; r < 4; r++) {
        int j4 = lane + 32 * r;
        float4 x = dp[j4];
        int j = j4 * 8;
        float p0 = x.x * sC[j + 0] + x.y * sC[j + 2] + x.z * sC[j + 4] + x.w * sC[j + 6];
        float p1 = x.x * sC[j + 1] + x.y * sC[j + 3] + x.z * sC[j + 5] + x.w * sC[j + 7];
        float y0 = p0 - c0, t0 = d0 + y0; c0 = (t0 - d0) - y0; d0 = t0;
        float y1 = p1 - c1, t1 = d1 + y1; c1 = (t1 - d1) - y1; d1 = t1;
    }
    d0 += c0; d1 += c1;
#pragma unroll
    for (int off = 16; off; off >>= 1) {
        d0 += __shfl_xor_sync(0xffffffffu, d0, off);
        d1 += __shfl_xor_sync(0xffffffffu, d1, off);
    }
    if (lane == 0) {
        double sd0 = g_d[tloc * 2], sd1 = g_d[tloc * 2 + 1];
        uint32_t base = (uint32_t)(b * 8192 + 2 * tloc);
        float g00 = gumbel_at(ka0, ka1, base);
        float g01 = gumbel_at(ka0, ka1, base + 1u);
        float g10 = gumbel_at(kb0, kb1, base);
        float g11 = gumbel_at(kb0, kb1, base + 1u);
        float l00 = (float)((double)d0 + sd0 + cb[0][0]);
        float l01 = (float)((double)d1 + sd1 + cb[0][1]);
        float l10 = (float)((double)d0 + sd0 + cb[1][0]);
        float l11 = (float)((double)d1 + sd1 + cb[1][1]);
        int f0 = ((l00 + g00) >= (l01 + g01));
        int f1 = ((l10 + g10) >= (l11 + g11));
        g_mask[m] = f0 & f1;
    }
}

// ---------------- K: per-row stable exclusive scan --> sel indices -----------
__global__ __launch_bounds__(256)
void scan_kernel()
{
    const int b = blockIdx.x;
    const int tid = threadIdx.x;
    const int base = tid * 16;

    int m[16];
    int cnt = 0;
#pragma unroll
    for (int q = 0; q < 16; q++) {
        m[q] = g_mask[b * 4096 + base + q];
        cnt += m[q];
    }

    const int lane = tid & 31, warp = tid >> 5;
    int v = cnt;
#pragma unroll
    for (int off = 1; off < 32; off <<= 1) {
        int n2 = __shfl_up_sync(0xffffffffu, v, off);
        if (lane >= off) v += n2;
    }
    __shared__ int wtot[8];
    if (lane == 31) wtot[warp] = v;
    __syncthreads();
    int woff = 0;
    for (int w = 0; w < warp; w++) woff += wtot[w];
    int excl = woff + v - cnt;

    int pos = excl;
#pragma unroll
    for (int q = 0; q < 16; q++) {
        if (m[q]) g_sel[b * 4096 + pos++] = base + q;
    }
    if (tid == 255) g_lens[b] = excl + cnt;
}

// ---------------- K: pack selected data rows -> bf16x2 splits ----------------
__global__ __launch_bounds__(256)
void packA_kernel(const float* __restrict__ data)
{
    const int tid = threadIdx.x;
    const int rl = tid >> 7;                 // 0..1 row within block
    const int c4 = tid & 127;                // float4 index in row
    const int p = blockIdx.x * 2 + rl;       // packed row 0..32767
    const int b = p >> 12, k = p & 4095;
    if (k >= g_lens[b]) return;
    const int t = g_sel[p];
    float4 v = ((const float4*)(data + ((size_t)(b << 12) + t) * 512))[c4];
    float x[4] = {v.x, v.y, v.z, v.w};
    __nv_bfloat16 h1[4], h2[4];
#pragma unroll
    for (int i = 0; i < 4; i++) {
        h1[i] = __float2bfloat16(x[i]);
        float r = x[i] - __bfloat162float(h1[i]);
        h2[i] = __float2bfloat16(r);
    }
    size_t o4 = (size_t)p * 128 + c4;
    uint2 u;
    __nv_bfloat162 pk;
#define PACK(dst, h) \
    pk = __halves2bfloat162((h)[0], (h)[1]); u.x = *(uint32_t*)&pk; \
    pk = __halves2bfloat162((h)[2], (h)[3]); u.y = *(uint32_t*)&pk; \
    ((uint2*)(dst))[o4] = u;
    PACK(g_A1, h1) PACK(g_A2, h2)
#undef PACK
}

// ---------------- K: mma.sync bf16x2 GEMM over packed rows -> out ------------
// CTA 128x128, 256 thr (8 warps, warp 32x64), K chunks of 32, double-buffered.
// SMEM rows padded to 40 bf16 (80B) -> conflict-free ldmatrix, 16B aligned.
#define ROWB 80
#define MATB (128 * ROWB)          // 10240 B per matrix
#define STAGEB (4 * MATB)          // 40960 B per stage (A1,A2,W1,W2)
#define GEMM_SMEM (2 * STAGEB)     // 81920 B

__global__ __launch_bounds__(256, 1)
void mma_gemm_kernel(const float* __restrict__ bias, float* __restrict__ out)
{
    const int n0 = blockIdx.x * 128;
    const int m0 = blockIdx.y * 128;
    const int len = g_lens[m0 >> 12];
    if ((m0 & 4095) >= len) return;          // whole m-block beyond packed length

    extern __shared__ char smem[];
    const uint32_t sb = smem_to_u32(smem);
    const int tid = threadIdx.x;
    const int lane = tid & 31;
    const int w = tid >> 5;
    const int wm = w & 3;          // 4 m-strips of 32
    const int wn = w >> 2;         // 2 n-strips of 64

    const __nv_bfloat16* gmat[4] = {g_A1, g_A2, g_W1, g_W2};

    auto issue_copy = [&](int ch, int st) {
        const int k0 = ch * 32;
#pragma unroll
        for (int it = 0; it < 8; it++) {
            int idx = tid + it * 256;           // 0..2047
            int mi = idx >> 9;                  // matrix 0..3
            int r  = (idx >> 2) & 127;          // row in tile
            int c  = idx & 3;                   // 16B chunk in row
            int grow = ((mi < 2) ? m0 : n0) + r;
            const __nv_bfloat16* gp = gmat[mi] + (size_t)grow * 512 + k0 + c * 8;
            cpasync16(sb + st * STAGEB + mi * MATB + r * ROWB + c * 16, gp);
        }
        asm volatile("cp.async.commit_group;" ::: "memory");
    };

    float facc[2][8][4];
#pragma unroll
    for (int a = 0; a < 2; a++)
#pragma unroll
        for (int b = 0; b < 8; b++)
#pragma unroll
            for (int c = 0; c < 4; c++) facc[a][b][c] = 0.f;

    issue_copy(0, 0);

    const int rsel = lane & 15;
    const int chalf = (lane >> 4) << 4;     // 0 or 16 bytes

    for (int ch = 0; ch < 16; ch++) {
        const int st = ch & 1;
        asm volatile("cp.async.wait_group 0;" ::: "memory");
        __syncthreads();
        if (ch < 15) issue_copy(ch + 1, st ^ 1);

        const uint32_t bst = sb + st * STAGEB;
#pragma unroll
        for (int ks = 0; ks < 2; ks++) {
            const int colb = ks * 32 + chalf;
            uint32_t fa[2][2][4], fb[2][4][4];
#pragma unroll
            for (int sp = 0; sp < 2; sp++) {
#pragma unroll
                for (int mt = 0; mt < 2; mt++)
                    ldm_x4(fa[sp][mt],
                           bst + sp * MATB + (wm * 32 + mt * 16 + rsel) * ROWB + colb);
#pragma unroll
                for (int ng = 0; ng < 4; ng++)
                    ldm_x4(fb[sp][ng],
                           bst + (2 + sp) * MATB + (wn * 64 + ng * 16 + rsel) * ROWB + colb);
            }
            // products: A1*W1, A1*W2, A2*W1  (A2*W2 ~ 2^-18 rel, omitted)
            const int pa[3] = {0, 0, 1};
            const int pb[3] = {0, 1, 0};
#pragma unroll
            for (int p = 0; p < 3; p++)
#pragma unroll
                for (int mt = 0; mt < 2; mt++)
#pragma unroll
                    for (int ng = 0; ng < 4; ng++) {
                        mma16816(facc[mt][ng * 2 + 0], fa[pa[p]][mt],
                                 fb[pb[p]][ng][0], fb[pb[p]][ng][2]);
                        mma16816(facc[mt][ng * 2 + 1], fa[pa[p]][mt],
                                 fb[pb[p]][ng][1], fb[pb[p]][ng][3]);
                    }
        }
        __syncthreads();
    }

    // epilogue: per packed row m -> token t = g_sel[m]; out[m] = (acc+b+pe[t])*8
    int rowm[4], rowt[4];
    bool rok[4];
#pragma unroll
    for (int q = 0; q < 4; q++) {
        int mt = q >> 1, hh = q & 1;
        int m = m0 + wm * 32 + mt * 16 + (lane >> 2) + hh * 8;
        int k = m & 4095;
        rowm[q] = m;
        rok[q] = (k < len);
        rowt[q] = rok[q] ? g_sel[m] : 0;
    }

#pragma unroll
    for (int mt = 0; mt < 2; mt++)
#pragma unroll
        for (int nt = 0; nt < 8; nt++) {
            int n = n0 + wn * 64 + nt * 8 + (lane & 3) * 2;
            float b0 = bias[n], b1 = bias[n + 1];
            {
                int q = mt * 2;
                if (rok[q]) {
                    const float* pe = g_pe + (size_t)rowt[q] * 512 + n;
                    float2 v;
                    v.x = (facc[mt][nt][0] + b0 + pe[0]) * 8.0f;
                    v.y = (facc[mt][nt][1] + b1 + pe[1]) * 8.0f;
                    *(float2*)(out + (size_t)rowm[q] * 512 + n) = v;
                }
            }
            {
                int q = mt * 2 + 1;
                if (rok[q]) {
                    const float* pe = g_pe + (size_t)rowt[q] * 512 + n;
                    float2 v;
                    v.x = (facc[mt][nt][2] + b0 + pe[0]) * 8.0f;
                    v.y = (facc[mt][nt][3] + b1 + pe[1]) * 8.0f;
                    *(float2*)(out + (size_t)rowm[q] * 512 + n) = v;
                }
            }
        }
}

// ---------------- launch ------------------------------------------------------
extern "C" void kernel_launch(void* const* d_in, const int* in_sizes, int n_in,
                              void* d_out, int out_size)
{
    const float* data    = (const float*)d_in[0];
    const float* v0      = (const float*)d_in[1];
    const float* v1      = (const float*)d_in[2];
    const float* W_embed = (const float*)d_in[3];
    const float* b_embed = (const float*)d_in[4];
    const float* Wx      = (const float*)d_in[5];
    const float* Wv      = (const float*)d_in[6];
    const float* b_f     = (const float*)d_in[7];
    float* out = (float*)d_out;

    uint32_t ka0, ka1, kb0, kb1;
    threefry2x32(0u, 42u, 0u, 0u, ka0, ka1);
    threefry2x32(0u, 42u, 0u, 1u, kb0, kb1);

    cudaFuncSetAttribute(mma_gemm_kernel,
                         cudaFuncAttributeMaxDynamicSharedMemorySize, GEMM_SMEM);

    zero_kernel<<<16384, 256>>>((float4*)out);
    div_kernel<<<1, 256>>>();
    pe_kernel<<<4096, 256>>>();
    splitW_kernel<<<dim3(16, 16), dim3(32, 8)>>>(W_embed);
    cproj_kernel<<<4, 256>>>(W_embed, Wx);
    dtab_kernel<<<4096, 32>>>(b_embed, Wx);
    filter_kernel<<<4096, 256>>>(data, Wv, b_f, v0, v1, ka0, ka1, kb0, kb1);
    scan_kernel<<<8, 256>>>();
    packA_kernel<<<16384, 256>>>(data);
    mma_gemm_kernel<<<dim3(4, 256), 256, GEMM_SMEM>>>(b_embed, out);
}

// round 14
// speedup vs baseline: 3.7440x; 2.4810x over previous
#include <cuda_runtime.h>
#include <cuda_bf16.h>
#include <cstdint>
#include <math.h>

// Problem constants
#define BB 8
#define TT 4096
#define HH 512
#define MTOT (BB*TT)          // 32768 rows

// ---------------- scratch (static device globals; no allocation) -------------
__device__ __align__(16) float g_pe[(size_t)TT * HH];      // 8 MB
__device__ float  g_div[256];
__device__ float  g_C[HH * 2];       // 8 * W_embed @ Wx  (fp32, Kahan-computed)
__device__ double g_d[TT * 2];       // 8 * (b_embed + pe[t]) @ Wx
__device__ __align__(16) float g_gum[2][65536];  // precomputed gumbel draws
__device__ int    g_mask[MTOT];
__device__ int    g_sel[MTOT];
__device__ int    g_lens[BB];
__device__ __align__(16) __nv_bfloat16 g_A1[(size_t)MTOT * HH];  // packed rows only
__device__ __align__(16) __nv_bfloat16 g_A2[(size_t)MTOT * HH];
__device__ __align__(16) __nv_bfloat16 g_W1[HH * HH];            // transposed [n][k]
__device__ __align__(16) __nv_bfloat16 g_W2[HH * HH];

// ---------------- helpers ----------------------------------------------------
__device__ __forceinline__ uint32_t smem_to_u32(const void* p) {
    uint32_t a;
    asm("{ .reg .u64 t; cvta.to.shared.u64 t, %1; cvt.u32.u64 %0, t; }" : "=r"(a) : "l"(p));
    return a;
}
__device__ __forceinline__ void cpasync16(uint32_t sa, const void* g) {
    asm volatile("cp.async.cg.shared.global [%0], [%1], 16;" :: "r"(sa), "l"(g));
}
__device__ __forceinline__ void ldm_x4(uint32_t* r, uint32_t addr) {
    asm volatile("ldmatrix.sync.aligned.m8n8.x4.shared.b16 {%0,%1,%2,%3}, [%4];"
        : "=r"(r[0]), "=r"(r[1]), "=r"(r[2]), "=r"(r[3]) : "r"(addr));
}
__device__ __forceinline__ void mma16816(float* d, const uint32_t* a,
                                         uint32_t b0, uint32_t b1) {
    asm volatile("mma.sync.aligned.m16n8k16.row.col.f32.bf16.bf16.f32 "
        "{%0,%1,%2,%3}, {%4,%5,%6,%7}, {%8,%9}, {%0,%1,%2,%3};"
        : "+f"(d[0]), "+f"(d[1]), "+f"(d[2]), "+f"(d[3])
        : "r"(a[0]), "r"(a[1]), "r"(a[2]), "r"(a[3]), "r"(b0), "r"(b1));
}

// ---------------- threefry2x32 (Random123 / JAX-compatible) ------------------
__host__ __device__ __forceinline__
void threefry2x32(uint32_t k0, uint32_t k1, uint32_t x0, uint32_t x1,
                  uint32_t& o0, uint32_t& o1)
{
    uint32_t ks2 = k0 ^ k1 ^ 0x1BD11BDAu;
    x0 += k0; x1 += k1;
#define RND(r) { x0 += x1; x1 = (x1 << r) | (x1 >> (32 - r)); x1 ^= x0; }
    RND(13) RND(15) RND(26) RND(6)
    x0 += k1; x1 += ks2 + 1u;
    RND(17) RND(29) RND(16) RND(24)
    x0 += ks2; x1 += k0 + 2u;
    RND(13) RND(15) RND(26) RND(6)
    x0 += k0; x1 += k1 + 3u;
    RND(17) RND(29) RND(16) RND(24)
    x0 += k1; x1 += ks2 + 4u;
    RND(13) RND(15) RND(26) RND(6)
    x0 += ks2; x1 += k0 + 5u;
#undef RND
    o0 = x0; o1 = x1;
}

// gumbel draw, jax_threefry_partitionable=True: bits = o0 ^ o1 of (key, (0, idx))
__device__ __forceinline__
float gumbel_at(uint32_t k0, uint32_t k1, uint32_t idx)
{
    uint32_t o0, o1;
    threefry2x32(k0, k1, 0u, idx, o0, o1);
    uint32_t bits = o0 ^ o1;
    uint32_t fb = (bits >> 9) | 0x3f800000u;
    float f = __uint_as_float(fb) - 1.0f;
    float u = fmaxf(f, 1.17549435e-38f);
    float l1 = (float)log((double)u);
    return -(float)log((double)(-l1));
}

// ---------------- K: precompute all gumbel draws (all lanes active) ----------
__global__ __launch_bounds__(256)
void gumbel_kernel(uint32_t ka0, uint32_t ka1, uint32_t kb0, uint32_t kb1)
{
    uint32_t idx = blockIdx.x * 256 + threadIdx.x;   // 0..65535
    g_gum[0][idx] = gumbel_at(ka0, ka1, idx);
    g_gum[1][idx] = gumbel_at(kb0, kb1, idx);
}

// ---------------- K: inv-freq table ------------------------------------------
__global__ void div_kernel()
{
    int j = threadIdx.x;
    double c = -log(10000.0) / 512.0;
    float arg = (float)(2 * j) * (float)c;
    g_div[j] = (float)exp((double)arg);
}

// ---------------- K: PE table [4096, 512] ------------------------------------
__global__ __launch_bounds__(256) void pe_kernel()
{
    int t = blockIdx.x;
    float tf = (float)t;
    for (int n = threadIdx.x; n < 512; n += 256) {
        float ang = tf * g_div[n >> 1];
        g_pe[(size_t)t * 512 + n] = (n & 1) ? cosf(ang) : sinf(ang);
    }
}

// ---------------- K: zero the output -----------------------------------------
__global__ __launch_bounds__(256) void zero_kernel(float4* __restrict__ out)
{
    out[(size_t)blockIdx.x * 256 + threadIdx.x] = make_float4(0.f, 0.f, 0.f, 0.f);
}

// ---------------- K: C = 8 * W_embed @ Wx  (Kahan fp32) ----------------------
__global__ __launch_bounds__(256) void cproj_kernel(const float* __restrict__ W,
                                                    const float* __restrict__ Wx)
{
    int idx = blockIdx.x * 256 + threadIdx.x;   // 0..1023
    int k = idx >> 1, i = idx & 1;
    float s = 0.f, c = 0.f;
    for (int j = 0; j < 512; j++) {
        float p = W[(size_t)k * 512 + j] * Wx[j * 2 + i];
        float y = p - c, t = s + y; c = (t - s) - y; s = t;
    }
    g_C[idx] = 8.0f * (s + c);
}

// ---------------- K: d[t] = 8 * (b_embed + pe[t]) @ Wx  (Kahan fp32) ---------
__global__ __launch_bounds__(32) void dtab_kernel(const float* __restrict__ bias,
                                                  const float* __restrict__ Wx)
{
    int t = blockIdx.x, lane = threadIdx.x;
    float s0 = 0.f, c0 = 0.f, s1 = 0.f, c1 = 0.f;
    for (int j = lane; j < 512; j += 32) {
        float e = bias[j] + g_pe[(size_t)t * 512 + j];
        float p0 = e * Wx[2 * j];
        float p1 = e * Wx[2 * j + 1];
        float y0 = p0 - c0, t0 = s0 + y0; c0 = (t0 - s0) - y0; s0 = t0;
        float y1 = p1 - c1, t1 = s1 + y1; c1 = (t1 - s1) - y1; s1 = t1;
    }
    s0 += c0; s1 += c1;
#pragma unroll
    for (int off = 16; off; off >>= 1) {
        s0 += __shfl_xor_sync(0xffffffffu, s0, off);
        s1 += __shfl_xor_sync(0xffffffffu, s1, off);
    }
    if (lane == 0) { g_d[t * 2] = 8.0 * (double)s0; g_d[t * 2 + 1] = 8.0 * (double)s1; }
}

// ---------------- K: split + transpose W into bf16x2 [n][k] ------------------
__global__ void splitW_kernel(const float* __restrict__ W)
{
    __shared__ float ts[32][33];
    int kt = blockIdx.y * 32, nt = blockIdx.x * 32;
    int tx = threadIdx.x, ty = threadIdx.y;   // 32 x 8
    for (int i = ty; i < 32; i += 8)
        ts[i][tx] = W[(size_t)(kt + i) * 512 + nt + tx];
    __syncthreads();
    for (int i = ty; i < 32; i += 8) {
        float x = ts[tx][i];   // = W[kt+tx][nt+i]
        __nv_bfloat16 h1 = __float2bfloat16(x);
        float r = x - __bfloat162float(h1);
        __nv_bfloat16 h2 = __float2bfloat16(r);
        size_t o = (size_t)(nt + i) * 512 + kt + tx;
        g_W1[o] = h1; g_W2[o] = h2;
    }
}

// ---------------- K: filter — logits from data directly, gumbel-max ----------
// logit_i(token m=b*4096+t) = data_m . C_i + d[t][i] + (v_f @ Wv)_i + bf_i
__global__ __launch_bounds__(256)
void filter_kernel(const float* __restrict__ data,
                   const float* __restrict__ Wv,   // [512,2]
                   const float* __restrict__ bf,   // [2]
                   const float* __restrict__ v0,   // [8,512]
                   const float* __restrict__ v1)   // [8,512]
{
    const int tid = threadIdx.x;
    const int b = blockIdx.x >> 9;            // 512 blocks per batch row
    __shared__ float sC[1024];
    __shared__ double cb[2][2];

    for (int k = tid; k < 1024; k += 256) sC[k] = g_C[k];

    if (tid < 32) {
        // v @ Wv in Kahan fp32 (small: 2x512 per batch)
        float s00 = 0, e00 = 0, s01 = 0, e01 = 0, s10 = 0, e10 = 0, s11 = 0, e11 = 0;
        for (int k = tid; k < 512; k += 32) {
            float w0 = Wv[2 * k], w1 = Wv[2 * k + 1];
            float a = v0[b * 512 + k], c = v1[b * 512 + k];
#define KA(s, e, p) { float y = (p) - e, t = s + y; e = (t - s) - y; s = t; }
            KA(s00, e00, a * w0) KA(s01, e01, a * w1)
            KA(s10, e10, c * w0) KA(s11, e11, c * w1)
#undef KA
        }
        s00 += e00; s01 += e01; s10 += e10; s11 += e11;
#pragma unroll
        for (int off = 16; off; off >>= 1) {
            s00 += __shfl_xor_sync(0xffffffffu, s00, off);
            s01 += __shfl_xor_sync(0xffffffffu, s01, off);
            s10 += __shfl_xor_sync(0xffffffffu, s10, off);
            s11 += __shfl_xor_sync(0xffffffffu, s11, off);
        }
        if (tid == 0) {
            cb[0][0] = (double)s00 + (double)bf[0]; cb[0][1] = (double)s01 + (double)bf[1];
            cb[1][0] = (double)s10 + (double)bf[0]; cb[1][1] = (double)s11 + (double)bf[1];
        }
    }
    __syncthreads();

    const int warp = tid >> 5, lane = tid & 31;
    const int m = blockIdx.x * 8 + warp;      // global token row
    const int tloc = m & 4095;
    const float4* dp = (const float4*)(data + (size_t)m * 512);

    // Kahan fp32 dot (proven mask-exact in R8)
    float d0 = 0.f, c0 = 0.f, d1 = 0.f, c1 = 0.f;
#pragma unroll
    for (int r = 0; r < 4; r++) {
        int j4 = lane + 32 * r;
        float4 x = dp[j4];
        int j = j4 * 8;
        float p0 = x.x * sC[j + 0] + x.y * sC[j + 2] + x.z * sC[j + 4] + x.w * sC[j + 6];
        float p1 = x.x * sC[j + 1] + x.y * sC[j + 3] + x.z * sC[j + 5] + x.w * sC[j + 7];
        float y0 = p0 - c0, t0 = d0 + y0; c0 = (t0 - d0) - y0; d0 = t0;
        float y1 = p1 - c1, t1 = d1 + y1; c1 = (t1 - d1) - y1; d1 = t1;
    }
    d0 += c0; d1 += c1;
#pragma unroll
    for (int off = 16; off; off >>= 1) {
        d0 += __shfl_xor_sync(0xffffffffu, d0, off);
        d1 += __shfl_xor_sync(0xffffffffu, d1, off);
    }
    if (lane == 0) {
        double sd0 = g_d[tloc * 2], sd1 = g_d[tloc * 2 + 1];
        uint32_t base = (uint32_t)(b * 8192 + 2 * tloc);
        float g00 = g_gum[0][base],     g01 = g_gum[0][base + 1u];
        float g10 = g_gum[1][base],     g11 = g_gum[1][base + 1u];
        float l00 = (float)((double)d0 + sd0 + cb[0][0]);
        float l01 = (float)((double)d1 + sd1 + cb[0][1]);
        float l10 = (float)((double)d0 + sd0 + cb[1][0]);
        float l11 = (float)((double)d1 + sd1 + cb[1][1]);
        int f0 = ((l00 + g00) >= (l01 + g01));
        int f1 = ((l10 + g10) >= (l11 + g11));
        g_mask[m] = f0 & f1;
    }
}

// ---------------- K: per-row stable exclusive scan --> sel indices -----------
__global__ __launch_bounds__(256)
void scan_kernel()
{
    const int b = blockIdx.x;
    const int tid = threadIdx.x;
    const int base = tid * 16;

    int m[16];
    int cnt = 0;
#pragma unroll
    for (int q = 0; q < 16; q++) {
        m[q] = g_mask[b * 4096 + base + q];
        cnt += m[q];
    }

    const int lane = tid & 31, warp = tid >> 5;
    int v = cnt;
#pragma unroll
    for (int off = 1; off < 32; off <<= 1) {
        int n2 = __shfl_up_sync(0xffffffffu, v, off);
        if (lane >= off) v += n2;
    }
    __shared__ int wtot[8];
    if (lane == 31) wtot[warp] = v;
    __syncthreads();
    int woff = 0;
    for (int w = 0; w < warp; w++) woff += wtot[w];
    int excl = woff + v - cnt;

    int pos = excl;
#pragma unroll
    for (int q = 0; q < 16; q++) {
        if (m[q]) g_sel[b * 4096 + pos++] = base + q;
    }
    if (tid == 255) g_lens[b] = excl + cnt;
}

// ---------------- K: pack selected data rows -> bf16x2 splits ----------------
__global__ __launch_bounds__(256)
void packA_kernel(const float* __restrict__ data)
{
    const int tid = threadIdx.x;
    const int rl = tid >> 7;                 // 0..1 row within block
    const int c4 = tid & 127;                // float4 index in row
    const int p = blockIdx.x * 2 + rl;       // packed row 0..32767
    const int b = p >> 12, k = p & 4095;
    if (k >= g_lens[b]) return;
    const int t = g_sel[p];
    float4 v = ((const float4*)(data + ((size_t)(b << 12) + t) * 512))[c4];
    float x[4] = {v.x, v.y, v.z, v.w};
    __nv_bfloat16 h1[4], h2[4];
#pragma unroll
    for (int i = 0; i < 4; i++) {
        h1[i] = __float2bfloat16(x[i]);
        float r = x[i] - __bfloat162float(h1[i]);
        h2[i] = __float2bfloat16(r);
    }
    size_t o4 = (size_t)p * 128 + c4;
    uint2 u;
    __nv_bfloat162 pk;
#define PACK(dst, h) \
    pk = __halves2bfloat162((h)[0], (h)[1]); u.x = *(uint32_t*)&pk; \
    pk = __halves2bfloat162((h)[2], (h)[3]); u.y = *(uint32_t*)&pk; \
    ((uint2*)(dst))[o4] = u;
    PACK(g_A1, h1) PACK(g_A2, h2)
#undef PACK
}

// ---------------- K: mma.sync bf16x2 GEMM over packed rows -> out ------------
// CTA 128x128, 256 thr (8 warps, warp 32x64), K chunks of 32, double-buffered.
// SMEM rows padded to 40 bf16 (80B) -> conflict-free ldmatrix, 16B aligned.
#define ROWB 80
#define MATB (128 * ROWB)          // 10240 B per matrix
#define STAGEB (4 * MATB)          // 40960 B per stage (A1,A2,W1,W2)
#define GEMM_SMEM (2 * STAGEB)     // 81920 B

__global__ __launch_bounds__(256, 1)
void mma_gemm_kernel(const float* __restrict__ bias, float* __restrict__ out)
{
    const int n0 = blockIdx.x * 128;
    const int m0 = blockIdx.y * 128;
    const int len = g_lens[m0 >> 12];
    if ((m0 & 4095) >= len) return;          // whole m-block beyond packed length

    extern __shared__ char smem[];
    const uint32_t sb = smem_to_u32(smem);
    const int tid = threadIdx.x;
    const int lane = tid & 31;
    const int w = tid >> 5;
    const int wm = w & 3;          // 4 m-strips of 32
    const int wn = w >> 2;         // 2 n-strips of 64

    const __nv_bfloat16* gmat[4] = {g_A1, g_A2, g_W1, g_W2};

    auto issue_copy = [&](int ch, int st) {
        const int k0 = ch * 32;
#pragma unroll
        for (int it = 0; it < 8; it++) {
            int idx = tid + it * 256;           // 0..2047
            int mi = idx >> 9;                  // matrix 0..3
            int r  = (idx >> 2) & 127;          // row in tile
            int c  = idx & 3;                   // 16B chunk in row
            int grow = ((mi < 2) ? m0 : n0) + r;
            const __nv_bfloat16* gp = gmat[mi] + (size_t)grow * 512 + k0 + c * 8;
            cpasync16(sb + st * STAGEB + mi * MATB + r * ROWB + c * 16, gp);
        }
        asm volatile("cp.async.commit_group;" ::: "memory");
    };

    float facc[2][8][4];
#pragma unroll
    for (int a = 0; a < 2; a++)
#pragma unroll
        for (int b = 0; b < 8; b++)
#pragma unroll
            for (int c = 0; c < 4; c++) facc[a][b][c] = 0.f;

    issue_copy(0, 0);

    const int rsel = lane & 15;
    const int chalf = (lane >> 4) << 4;     // 0 or 16 bytes

    for (int ch = 0; ch < 16; ch++) {
        const int st = ch & 1;
        asm volatile("cp.async.wait_group 0;" ::: "memory");
        __syncthreads();
        if (ch < 15) issue_copy(ch + 1, st ^ 1);

        const uint32_t bst = sb + st * STAGEB;
#pragma unroll
        for (int ks = 0; ks < 2; ks++) {
            const int colb = ks * 32 + chalf;
            uint32_t fa[2][2][4], fb[2][4][4];
#pragma unroll
            for (int sp = 0; sp < 2; sp++) {
#pragma unroll
                for (int mt = 0; mt < 2; mt++)
                    ldm_x4(fa[sp][mt],
                           bst + sp * MATB + (wm * 32 + mt * 16 + rsel) * ROWB + colb);
#pragma unroll
                for (int ng = 0; ng < 4; ng++)
                    ldm_x4(fb[sp][ng],
                           bst + (2 + sp) * MATB + (wn * 64 + ng * 16 + rsel) * ROWB + colb);
            }
            // products: A1*W1, A1*W2, A2*W1  (A2*W2 ~ 2^-18 rel, omitted)
            const int pa[3] = {0, 0, 1};
            const int pb[3] = {0, 1, 0};
#pragma unroll
            for (int p = 0; p < 3; p++)
#pragma unroll
                for (int mt = 0; mt < 2; mt++)
#pragma unroll
                    for (int ng = 0; ng < 4; ng++) {
                        mma16816(facc[mt][ng * 2 + 0], fa[pa[p]][mt],
                                 fb[pb[p]][ng][0], fb[pb[p]][ng][2]);
                        mma16816(facc[mt][ng * 2 + 1], fa[pa[p]][mt],
                                 fb[pb[p]][ng][1], fb[pb[p]][ng][3]);
                    }
        }
        __syncthreads();
    }

    // epilogue: per packed row m -> token t = g_sel[m]; out[m] = (acc+b+pe[t])*8
    int rowm[4], rowt[4];
    bool rok[4];
#pragma unroll
    for (int q = 0; q < 4; q++) {
        int mt = q >> 1, hh = q & 1;
        int m = m0 + wm * 32 + mt * 16 + (lane >> 2) + hh * 8;
        int k = m & 4095;
        rowm[q] = m;
        rok[q] = (k < len);
        rowt[q] = rok[q] ? g_sel[m] : 0;
    }

#pragma unroll
    for (int mt = 0; mt < 2; mt++)
#pragma unroll
        for (int nt = 0; nt < 8; nt++) {
            int n = n0 + wn * 64 + nt * 8 + (lane & 3) * 2;
            float b0 = bias[n], b1 = bias[n + 1];
            {
                int q = mt * 2;
                if (rok[q]) {
                    const float* pe = g_pe + (size_t)rowt[q] * 512 + n;
                    float2 v;
                    v.x = (facc[mt][nt][0] + b0 + pe[0]) * 8.0f;
                    v.y = (facc[mt][nt][1] + b1 + pe[1]) * 8.0f;
                    *(float2*)(out + (size_t)rowm[q] * 512 + n) = v;
                }
            }
            {
                int q = mt * 2 + 1;
                if (rok[q]) {
                    const float* pe = g_pe + (size_t)rowt[q] * 512 + n;
                    float2 v;
                    v.x = (facc[mt][nt][2] + b0 + pe[0]) * 8.0f;
                    v.y = (facc[mt][nt][3] + b1 + pe[1]) * 8.0f;
                    *(float2*)(out + (size_t)rowm[q] * 512 + n) = v;
                }
            }
        }
}

// ---------------- launch ------------------------------------------------------
extern "C" void kernel_launch(void* const* d_in, const int* in_sizes, int n_in,
                              void* d_out, int out_size)
{
    const float* data    = (const float*)d_in[0];
    const float* v0      = (const float*)d_in[1];
    const float* v1      = (const float*)d_in[2];
    const float* W_embed = (const float*)d_in[3];
    const float* b_embed = (const float*)d_in[4];
    const float* Wx      = (const float*)d_in[5];
    const float* Wv      = (const float*)d_in[6];
    const float* b_f     = (const float*)d_in[7];
    float* out = (float*)d_out;

    uint32_t ka0, ka1, kb0, kb1;
    threefry2x32(0u, 42u, 0u, 0u, ka0, ka1);
    threefry2x32(0u, 42u, 0u, 1u, kb0, kb1);

    cudaFuncSetAttribute(mma_gemm_kernel,
                         cudaFuncAttributeMaxDynamicSharedMemorySize, GEMM_SMEM);

    zero_kernel<<<16384, 256>>>((float4*)out);
    gumbel_kernel<<<256, 256>>>(ka0, ka1, kb0, kb1);
    div_kernel<<<1, 256>>>();
    pe_kernel<<<4096, 256>>>();
    splitW_kernel<<<dim3(16, 16), dim3(32, 8)>>>(W_embed);
    cproj_kernel<<<4, 256>>>(W_embed, Wx);
    dtab_kernel<<<4096, 32>>>(b_embed, Wx);
    filter_kernel<<<4096, 256>>>(data, Wv, b_f, v0, v1);
    scan_kernel<<<8, 256>>>();
    packA_kernel<<<16384, 256>>>(data);
    mma_gemm_kernel<<<dim3(4, 256), 256, GEMM_SMEM>>>(b_embed, out);
}

// round 15
// speedup vs baseline: 4.0482x; 1.0813x over previous
#include <cuda_runtime.h>
#include <cuda_bf16.h>
#include <cstdint>
#include <math.h>

// Problem constants
#define BB 8
#define TT 4096
#define HH 512
#define MTOT (BB*TT)          // 32768 rows

// ---------------- scratch (static device globals; no allocation) -------------
__device__ __align__(16) float g_pe[(size_t)TT * HH];      // 8 MB
__device__ float  g_div[256];
__device__ float  g_C[HH * 2];       // 8 * W_embed @ Wx  (fp32, Kahan-computed)
__device__ double g_d[TT * 2];       // 8 * (b_embed + pe[t]) @ Wx
__device__ __align__(16) float g_gum[2][65536];  // precomputed gumbel draws
__device__ int    g_mask[MTOT];
__device__ int    g_sel[MTOT];
__device__ int    g_lens[BB];
__device__ __align__(16) __nv_bfloat16 g_A1[(size_t)MTOT * HH];  // packed rows only
__device__ __align__(16) __nv_bfloat16 g_A2[(size_t)MTOT * HH];
__device__ __align__(16) __nv_bfloat16 g_W1[HH * HH];            // transposed [n][k]
__device__ __align__(16) __nv_bfloat16 g_W2[HH * HH];

// ---------------- helpers ----------------------------------------------------
__device__ __forceinline__ uint32_t smem_to_u32(const void* p) {
    uint32_t a;
    asm("{ .reg .u64 t; cvta.to.shared.u64 t, %1; cvt.u32.u64 %0, t; }" : "=r"(a) : "l"(p));
    return a;
}
__device__ __forceinline__ void cpasync16(uint32_t sa, const void* g) {
    asm volatile("cp.async.cg.shared.global [%0], [%1], 16;" :: "r"(sa), "l"(g));
}
__device__ __forceinline__ void ldm_x4(uint32_t* r, uint32_t addr) {
    asm volatile("ldmatrix.sync.aligned.m8n8.x4.shared.b16 {%0,%1,%2,%3}, [%4];"
        : "=r"(r[0]), "=r"(r[1]), "=r"(r[2]), "=r"(r[3]) : "r"(addr));
}
__device__ __forceinline__ void mma16816(float* d, const uint32_t* a,
                                         uint32_t b0, uint32_t b1) {
    asm volatile("mma.sync.aligned.m16n8k16.row.col.f32.bf16.bf16.f32 "
        "{%0,%1,%2,%3}, {%4,%5,%6,%7}, {%8,%9}, {%0,%1,%2,%3};"
        : "+f"(d[0]), "+f"(d[1]), "+f"(d[2]), "+f"(d[3])
        : "r"(a[0]), "r"(a[1]), "r"(a[2]), "r"(a[3]), "r"(b0), "r"(b1));
}

// ---------------- threefry2x32 (Random123 / JAX-compatible) ------------------
__host__ __device__ __forceinline__
void threefry2x32(uint32_t k0, uint32_t k1, uint32_t x0, uint32_t x1,
                  uint32_t& o0, uint32_t& o1)
{
    uint32_t ks2 = k0 ^ k1 ^ 0x1BD11BDAu;
    x0 += k0; x1 += k1;
#define RND(r) { x0 += x1; x1 = (x1 << r) | (x1 >> (32 - r)); x1 ^= x0; }
    RND(13) RND(15) RND(26) RND(6)
    x0 += k1; x1 += ks2 + 1u;
    RND(17) RND(29) RND(16) RND(24)
    x0 += ks2; x1 += k0 + 2u;
    RND(13) RND(15) RND(26) RND(6)
    x0 += k0; x1 += k1 + 3u;
    RND(17) RND(29) RND(16) RND(24)
    x0 += k1; x1 += ks2 + 4u;
    RND(13) RND(15) RND(26) RND(6)
    x0 += ks2; x1 += k0 + 5u;
#undef RND
    o0 = x0; o1 = x1;
}

// gumbel draw, jax_threefry_partitionable=True: bits = o0 ^ o1 of (key, (0, idx))
__device__ __forceinline__
float gumbel_at(uint32_t k0, uint32_t k1, uint32_t idx)
{
    uint32_t o0, o1;
    threefry2x32(k0, k1, 0u, idx, o0, o1);
    uint32_t bits = o0 ^ o1;
    uint32_t fb = (bits >> 9) | 0x3f800000u;
    float f = __uint_as_float(fb) - 1.0f;
    float u = fmaxf(f, 1.17549435e-38f);
    float l1 = (float)log((double)u);
    return -(float)log((double)(-l1));
}

// ---------------- K: precompute all gumbel draws (all lanes active) ----------
__global__ __launch_bounds__(256)
void gumbel_kernel(uint32_t ka0, uint32_t ka1, uint32_t kb0, uint32_t kb1)
{
    uint32_t idx = blockIdx.x * 256 + threadIdx.x;   // 0..65535
    g_gum[0][idx] = gumbel_at(ka0, ka1, idx);
    g_gum[1][idx] = gumbel_at(kb0, kb1, idx);
}

// ---------------- K: inv-freq table ------------------------------------------
__global__ void div_kernel()
{
    int j = threadIdx.x;
    double c = -log(10000.0) / 512.0;
    float arg = (float)(2 * j) * (float)c;
    g_div[j] = (float)exp((double)arg);
}

// ---------------- K: PE table [4096, 512] ------------------------------------
__global__ __launch_bounds__(256) void pe_kernel()
{
    int t = blockIdx.x;
    float tf = (float)t;
    for (int n = threadIdx.x; n < 512; n += 256) {
        float ang = tf * g_div[n >> 1];
        g_pe[(size_t)t * 512 + n] = (n & 1) ? cosf(ang) : sinf(ang);
    }
}

// ---------------- K: C = 8 * W_embed @ Wx  (Kahan fp32) ----------------------
__global__ __launch_bounds__(256) void cproj_kernel(const float* __restrict__ W,
                                                    const float* __restrict__ Wx)
{
    int idx = blockIdx.x * 256 + threadIdx.x;   // 0..1023
    int k = idx >> 1, i = idx & 1;
    float s = 0.f, c = 0.f;
    for (int j = 0; j < 512; j++) {
        float p = W[(size_t)k * 512 + j] * Wx[j * 2 + i];
        float y = p - c, t = s + y; c = (t - s) - y; s = t;
    }
    g_C[idx] = 8.0f * (s + c);
}

// ---------------- K: d[t] = 8 * (b_embed + pe[t]) @ Wx  (Kahan fp32) ---------
// 256-thread blocks, one token per warp (8 per block)
__global__ __launch_bounds__(256) void dtab_kernel(const float* __restrict__ bias,
                                                   const float* __restrict__ Wx)
{
    int warp = threadIdx.x >> 5, lane = threadIdx.x & 31;
    int t = blockIdx.x * 8 + warp;
    float s0 = 0.f, c0 = 0.f, s1 = 0.f, c1 = 0.f;
    for (int j = lane; j < 512; j += 32) {
        float e = bias[j] + g_pe[(size_t)t * 512 + j];
        float p0 = e * Wx[2 * j];
        float p1 = e * Wx[2 * j + 1];
        float y0 = p0 - c0, t0 = s0 + y0; c0 = (t0 - s0) - y0; s0 = t0;
        float y1 = p1 - c1, t1 = s1 + y1; c1 = (t1 - s1) - y1; s1 = t1;
    }
    s0 += c0; s1 += c1;
#pragma unroll
    for (int off = 16; off; off >>= 1) {
        s0 += __shfl_xor_sync(0xffffffffu, s0, off);
        s1 += __shfl_xor_sync(0xffffffffu, s1, off);
    }
    if (lane == 0) { g_d[t * 2] = 8.0 * (double)s0; g_d[t * 2 + 1] = 8.0 * (double)s1; }
}

// ---------------- K: split + transpose W into bf16x2 [n][k] ------------------
__global__ void splitW_kernel(const float* __restrict__ W)
{
    __shared__ float ts[32][33];
    int kt = blockIdx.y * 32, nt = blockIdx.x * 32;
    int tx = threadIdx.x, ty = threadIdx.y;   // 32 x 8
    for (int i = ty; i < 32; i += 8)
        ts[i][tx] = W[(size_t)(kt + i) * 512 + nt + tx];
    __syncthreads();
    for (int i = ty; i < 32; i += 8) {
        float x = ts[tx][i];   // = W[kt+tx][nt+i]
        __nv_bfloat16 h1 = __float2bfloat16(x);
        float r = x - __bfloat162float(h1);
        __nv_bfloat16 h2 = __float2bfloat16(r);
        size_t o = (size_t)(nt + i) * 512 + kt + tx;
        g_W1[o] = h1; g_W2[o] = h2;
    }
}

// ---------------- K: filter — logits from data directly, gumbel-max ----------
__global__ __launch_bounds__(256)
void filter_kernel(const float* __restrict__ data,
                   const float* __restrict__ Wv,   // [512,2]
                   const float* __restrict__ bf,   // [2]
                   const float* __restrict__ v0,   // [8,512]
                   const float* __restrict__ v1)   // [8,512]
{
    const int tid = threadIdx.x;
    const int b = blockIdx.x >> 9;            // 512 blocks per batch row
    __shared__ float sC[1024];
    __shared__ double cb[2][2];

    for (int k = tid; k < 1024; k += 256) sC[k] = g_C[k];

    if (tid < 32) {
        float s00 = 0, e00 = 0, s01 = 0, e01 = 0, s10 = 0, e10 = 0, s11 = 0, e11 = 0;
        for (int k = tid; k < 512; k += 32) {
            float w0 = Wv[2 * k], w1 = Wv[2 * k + 1];
            float a = v0[b * 512 + k], c = v1[b * 512 + k];
#define KA(s, e, p) { float y = (p) - e, t = s + y; e = (t - s) - y; s = t; }
            KA(s00, e00, a * w0) KA(s01, e01, a * w1)
            KA(s10, e10, c * w0) KA(s11, e11, c * w1)
#undef KA
        }
        s00 += e00; s01 += e01; s10 += e10; s11 += e11;
#pragma unroll
        for (int off = 16; off; off >>= 1) {
            s00 += __shfl_xor_sync(0xffffffffu, s00, off);
            s01 += __shfl_xor_sync(0xffffffffu, s01, off);
            s10 += __shfl_xor_sync(0xffffffffu, s10, off);
            s11 += __shfl_xor_sync(0xffffffffu, s11, off);
        }
        if (tid == 0) {
            cb[0][0] = (double)s00 + (double)bf[0]; cb[0][1] = (double)s01 + (double)bf[1];
            cb[1][0] = (double)s10 + (double)bf[0]; cb[1][1] = (double)s11 + (double)bf[1];
        }
    }
    __syncthreads();

    const int warp = tid >> 5, lane = tid & 31;
    const int m = blockIdx.x * 8 + warp;      // global token row
    const int tloc = m & 4095;
    const float4* dp = (const float4*)(data + (size_t)m * 512);

    // Kahan fp32 dot (proven mask-exact in R8)
    float d0 = 0.f, c0 = 0.f, d1 = 0.f, c1 = 0.f;
#pragma unroll
    for (int r = 0; r < 4; r++) {
        int j4 = lane + 32 * r;
        float4 x = dp[j4];
        int j = j4 * 8;
        float p0 = x.x * sC[j + 0] + x.y * sC[j + 2] + x.z * sC[j + 4] + x.w * sC[j + 6];
        float p1 = x.x * sC[j + 1] + x.y * sC[j + 3] + x.z * sC[j + 5] + x.w * sC[j + 7];
        float y0 = p0 - c0, t0 = d0 + y0; c0 = (t0 - d0) - y0; d0 = t0;
        float y1 = p1 - c1, t1 = d1 + y1; c1 = (t1 - d1) - y1; d1 = t1;
    }
    d0 += c0; d1 += c1;
#pragma unroll
    for (int off = 16; off; off >>= 1) {
        d0 += __shfl_xor_sync(0xffffffffu, d0, off);
        d1 += __shfl_xor_sync(0xffffffffu, d1, off);
    }
    if (lane == 0) {
        double sd0 = g_d[tloc * 2], sd1 = g_d[tloc * 2 + 1];
        uint32_t base = (uint32_t)(b * 8192 + 2 * tloc);
        float g00 = g_gum[0][base],     g01 = g_gum[0][base + 1u];
        float g10 = g_gum[1][base],     g11 = g_gum[1][base + 1u];
        float l00 = (float)((double)d0 + sd0 + cb[0][0]);
        float l01 = (float)((double)d1 + sd1 + cb[0][1]);
        float l10 = (float)((double)d0 + sd0 + cb[1][0]);
        float l11 = (float)((double)d1 + sd1 + cb[1][1]);
        int f0 = ((l00 + g00) >= (l01 + g01));
        int f1 = ((l10 + g10) >= (l11 + g11));
        g_mask[m] = f0 & f1;
    }
}

// ---------------- K: per-row stable exclusive scan --> sel indices -----------
__global__ __launch_bounds__(256)
void scan_kernel()
{
    const int b = blockIdx.x;
    const int tid = threadIdx.x;
    const int base = tid * 16;

    int m[16];
    int cnt = 0;
#pragma unroll
    for (int q = 0; q < 16; q++) {
        m[q] = g_mask[b * 4096 + base + q];
        cnt += m[q];
    }

    const int lane = tid & 31, warp = tid >> 5;
    int v = cnt;
#pragma unroll
    for (int off = 1; off < 32; off <<= 1) {
        int n2 = __shfl_up_sync(0xffffffffu, v, off);
        if (lane >= off) v += n2;
    }
    __shared__ int wtot[8];
    if (lane == 31) wtot[warp] = v;
    __syncthreads();
    int woff = 0;
    for (int w = 0; w < warp; w++) woff += wtot[w];
    int excl = woff + v - cnt;

    int pos = excl;
#pragma unroll
    for (int q = 0; q < 16; q++) {
        if (m[q]) g_sel[b * 4096 + pos++] = base + q;
    }
    if (tid == 255) g_lens[b] = excl + cnt;
}

// ---------------- K: pack selected rows -> bf16x2 splits, or pad out ---------
__global__ __launch_bounds__(256)
void packA_kernel(const float* __restrict__ data, float* __restrict__ out)
{
    const int tid = threadIdx.x;
    const int rl = tid >> 7;                 // 0..1 row within block
    const int c4 = tid & 127;                // float4 index in row
    const int p = blockIdx.x * 2 + rl;       // packed row 0..32767
    const int b = p >> 12, k = p & 4095;
    if (k >= g_lens[b]) {
        // padding row: zero the output directly (replaces zero_kernel)
        ((float4*)(out + (size_t)p * 512))[c4] = make_float4(0.f, 0.f, 0.f, 0.f);
        return;
    }
    const int t = g_sel[p];
    float4 v = ((const float4*)(data + ((size_t)(b << 12) + t) * 512))[c4];
    float x[4] = {v.x, v.y, v.z, v.w};
    __nv_bfloat16 h1[4], h2[4];
#pragma unroll
    for (int i = 0; i < 4; i++) {
        h1[i] = __float2bfloat16(x[i]);
        float r = x[i] - __bfloat162float(h1[i]);
        h2[i] = __float2bfloat16(r);
    }
    size_t o4 = (size_t)p * 128 + c4;
    uint2 u;
    __nv_bfloat162 pk;
#define PACK(dst, h) \
    pk = __halves2bfloat162((h)[0], (h)[1]); u.x = *(uint32_t*)&pk; \
    pk = __halves2bfloat162((h)[2], (h)[3]); u.y = *(uint32_t*)&pk; \
    ((uint2*)(dst))[o4] = u;
    PACK(g_A1, h1) PACK(g_A2, h2)
#undef PACK
}

// ---------------- K: mma.sync bf16x2 GEMM over packed rows -> out ------------
// CTA 128x128, 512 thr (16 warps, warp tile 32x32), K chunks of 32, dbl-buffer.
// SMEM rows padded to 40 bf16 (80B) -> conflict-free ldmatrix, 16B aligned.
#define ROWB 80
#define MATB (128 * ROWB)          // 10240 B per matrix
#define STAGEB (4 * MATB)          // 40960 B per stage (A1,A2,W1,W2)
#define GEMM_SMEM (2 * STAGEB)     // 81920 B

__global__ __launch_bounds__(512, 1)
void mma_gemm_kernel(const float* __restrict__ bias, float* __restrict__ out)
{
    const int n0 = blockIdx.x * 128;
    const int m0 = blockIdx.y * 128;
    const int len = g_lens[m0 >> 12];
    if ((m0 & 4095) >= len) return;          // whole m-block beyond packed length

    extern __shared__ char smem[];
    const uint32_t sb = smem_to_u32(smem);
    const int tid = threadIdx.x;
    const int lane = tid & 31;
    const int w = tid >> 5;
    const int wm = w & 3;          // 4 m-strips of 32
    const int wn = w >> 2;         // 4 n-strips of 32

    const __nv_bfloat16* gmat[4] = {g_A1, g_A2, g_W1, g_W2};

    auto issue_copy = [&](int ch, int st) {
        const int k0 = ch * 32;
#pragma unroll
        for (int it = 0; it < 4; it++) {
            int idx = tid + it * 512;           // 0..2047
            int mi = idx >> 9;                  // matrix 0..3
            int r  = (idx >> 2) & 127;          // row in tile
            int c  = idx & 3;                   // 16B chunk in row
            int grow = ((mi < 2) ? m0 : n0) + r;
            const __nv_bfloat16* gp = gmat[mi] + (size_t)grow * 512 + k0 + c * 8;
            cpasync16(sb + st * STAGEB + mi * MATB + r * ROWB + c * 16, gp);
        }
        asm volatile("cp.async.commit_group;" ::: "memory");
    };

    float facc[2][4][4];
#pragma unroll
    for (int a = 0; a < 2; a++)
#pragma unroll
        for (int b = 0; b < 4; b++)
#pragma unroll
            for (int c = 0; c < 4; c++) facc[a][b][c] = 0.f;

    issue_copy(0, 0);

    const int rsel = lane & 15;
    const int chalf = (lane >> 4) << 4;     // 0 or 16 bytes

    for (int ch = 0; ch < 16; ch++) {
        const int st = ch & 1;
        asm volatile("cp.async.wait_group 0;" ::: "memory");
        __syncthreads();
        if (ch < 15) issue_copy(ch + 1, st ^ 1);

        const uint32_t bst = sb + st * STAGEB;
#pragma unroll
        for (int ks = 0; ks < 2; ks++) {
            const int colb = ks * 32 + chalf;
            uint32_t fa[2][2][4], fb[2][2][4];
#pragma unroll
            for (int sp = 0; sp < 2; sp++) {
#pragma unroll
                for (int mt = 0; mt < 2; mt++)
                    ldm_x4(fa[sp][mt],
                           bst + sp * MATB + (wm * 32 + mt * 16 + rsel) * ROWB + colb);
#pragma unroll
                for (int ng = 0; ng < 2; ng++)
                    ldm_x4(fb[sp][ng],
                           bst + (2 + sp) * MATB + (wn * 32 + ng * 16 + rsel) * ROWB + colb);
            }
            // products: A1*W1, A1*W2, A2*W1  (A2*W2 ~ 2^-18 rel, omitted)
            const int pa[3] = {0, 0, 1};
            const int pb[3] = {0, 1, 0};
#pragma unroll
            for (int p = 0; p < 3; p++)
#pragma unroll
                for (int mt = 0; mt < 2; mt++)
#pragma unroll
                    for (int ng = 0; ng < 2; ng++) {
                        mma16816(facc[mt][ng * 2 + 0], fa[pa[p]][mt],
                                 fb[pb[p]][ng][0], fb[pb[p]][ng][2]);
                        mma16816(facc[mt][ng * 2 + 1], fa[pa[p]][mt],
                                 fb[pb[p]][ng][1], fb[pb[p]][ng][3]);
                    }
        }
        __syncthreads();
    }

    // epilogue: per packed row m -> token t = g_sel[m]; out[m] = (acc+b+pe[t])*8
    int rowm[4], rowt[4];
    bool rok[4];
#pragma unroll
    for (int q = 0; q < 4; q++) {
        int mt = q >> 1, hh = q & 1;
        int m = m0 + wm * 32 + mt * 16 + (lane >> 2) + hh * 8;
        int k = m & 4095;
        rowm[q] = m;
        rok[q] = (k < len);
        rowt[q] = rok[q] ? g_sel[m] : 0;
    }

#pragma unroll
    for (int mt = 0; mt < 2; mt++)
#pragma unroll
        for (int nt = 0; nt < 4; nt++) {
            int n = n0 + wn * 32 + nt * 8 + (lane & 3) * 2;
            float b0 = bias[n], b1 = bias[n + 1];
            {
                int q = mt * 2;
                if (rok[q]) {
                    const float* pe = g_pe + (size_t)rowt[q] * 512 + n;
                    float2 v;
                    v.x = (facc[mt][nt][0] + b0 + pe[0]) * 8.0f;
                    v.y = (facc[mt][nt][1] + b1 + pe[1]) * 8.0f;
                    *(float2*)(out + (size_t)rowm[q] * 512 + n) = v;
                }
            }
            {
                int q = mt * 2 + 1;
                if (rok[q]) {
                    const float* pe = g_pe + (size_t)rowt[q] * 512 + n;
                    float2 v;
                    v.x = (facc[mt][nt][2] + b0 + pe[0]) * 8.0f;
                    v.y = (facc[mt][nt][3] + b1 + pe[1]) * 8.0f;
                    *(float2*)(out + (size_t)rowm[q] * 512 + n) = v;
                }
            }
        }
}

// ---------------- launch ------------------------------------------------------
extern "C" void kernel_launch(void* const* d_in, const int* in_sizes, int n_in,
                              void* d_out, int out_size)
{
    const float* data    = (const float*)d_in[0];
    const float* v0      = (const float*)d_in[1];
    const float* v1      = (const float*)d_in[2];
    const float* W_embed = (const float*)d_in[3];
    const float* b_embed = (const float*)d_in[4];
    const float* Wx      = (const float*)d_in[5];
    const float* Wv      = (const float*)d_in[6];
    const float* b_f     = (const float*)d_in[7];
    float* out = (float*)d_out;

    uint32_t ka0, ka1, kb0, kb1;
    threefry2x32(0u, 42u, 0u, 0u, ka0, ka1);
    threefry2x32(0u, 42u, 0u, 1u, kb0, kb1);

    cudaFuncSetAttribute(mma_gemm_kernel,
                         cudaFuncAttributeMaxDynamicSharedMemorySize, GEMM_SMEM);

    gumbel_kernel<<<256, 256>>>(ka0, ka1, kb0, kb1);
    div_kernel<<<1, 256>>>();
    pe_kernel<<<4096, 256>>>();
    splitW_kernel<<<dim3(16, 16), dim3(32, 8)>>>(W_embed);
    cproj_kernel<<<4, 256>>>(W_embed, Wx);
    dtab_kernel<<<512, 256>>>(b_embed, Wx);
    filter_kernel<<<4096, 256>>>(data, Wv, b_f, v0, v1);
    scan_kernel<<<8, 256>>>();
    packA_kernel<<<16384, 256>>>(data, out);
    mma_gemm_kernel<<<dim3(4, 256), 512, GEMM_SMEM>>>(b_embed, out);
}

// round 16
// speedup vs baseline: 4.6747x; 1.1547x over previous
#include <cuda_runtime.h>
#include <cuda_bf16.h>
#include <cstdint>
#include <math.h>

// Problem constants
#define BB 8
#define TT 4096
#define HH 512
#define MTOT (BB*TT)          // 32768 rows

struct DivTab { float v[256]; };   // host-computed inv-freq table (1KB by-value)

// ---------------- scratch (static device globals; no allocation) -------------
__device__ __align__(16) float g_pe[(size_t)TT * HH];      // 8 MB
__device__ float  g_C[HH * 2];       // 8 * W_embed @ Wx  (fp32, Kahan-computed)
__device__ double g_d[TT * 2];       // 8 * (b_embed + pe[t]) @ Wx
__device__ __align__(16) float g_gum[2][65536];  // precomputed gumbel draws
__device__ int    g_mask[MTOT];
__device__ int    g_sel[MTOT];
__device__ int    g_lens[BB];
__device__ __align__(16) __nv_bfloat16 g_A1[(size_t)MTOT * HH];  // packed rows only
__device__ __align__(16) __nv_bfloat16 g_A2[(size_t)MTOT * HH];
__device__ __align__(16) __nv_bfloat16 g_W1[HH * HH];            // transposed [n][k]
__device__ __align__(16) __nv_bfloat16 g_W2[HH * HH];

// ---------------- helpers ----------------------------------------------------
__device__ __forceinline__ uint32_t smem_to_u32(const void* p) {
    uint32_t a;
    asm("{ .reg .u64 t; cvta.to.shared.u64 t, %1; cvt.u32.u64 %0, t; }" : "=r"(a) : "l"(p));
    return a;
}
__device__ __forceinline__ void cpasync16(uint32_t sa, const void* g) {
    asm volatile("cp.async.cg.shared.global [%0], [%1], 16;" :: "r"(sa), "l"(g));
}
__device__ __forceinline__ void ldm_x4(uint32_t* r, uint32_t addr) {
    asm volatile("ldmatrix.sync.aligned.m8n8.x4.shared.b16 {%0,%1,%2,%3}, [%4];"
        : "=r"(r[0]), "=r"(r[1]), "=r"(r[2]), "=r"(r[3]) : "r"(addr));
}
__device__ __forceinline__ void mma16816(float* d, const uint32_t* a,
                                         uint32_t b0, uint32_t b1) {
    asm volatile("mma.sync.aligned.m16n8k16.row.col.f32.bf16.bf16.f32 "
        "{%0,%1,%2,%3}, {%4,%5,%6,%7}, {%8,%9}, {%0,%1,%2,%3};"
        : "+f"(d[0]), "+f"(d[1]), "+f"(d[2]), "+f"(d[3])
        : "r"(a[0]), "r"(a[1]), "r"(a[2]), "r"(a[3]), "r"(b0), "r"(b1));
}

// ---------------- threefry2x32 (Random123 / JAX-compatible) ------------------
__host__ __device__ __forceinline__
void threefry2x32(uint32_t k0, uint32_t k1, uint32_t x0, uint32_t x1,
                  uint32_t& o0, uint32_t& o1)
{
    uint32_t ks2 = k0 ^ k1 ^ 0x1BD11BDAu;
    x0 += k0; x1 += k1;
#define RND(r) { x0 += x1; x1 = (x1 << r) | (x1 >> (32 - r)); x1 ^= x0; }
    RND(13) RND(15) RND(26) RND(6)
    x0 += k1; x1 += ks2 + 1u;
    RND(17) RND(29) RND(16) RND(24)
    x0 += ks2; x1 += k0 + 2u;
    RND(13) RND(15) RND(26) RND(6)
    x0 += k0; x1 += k1 + 3u;
    RND(17) RND(29) RND(16) RND(24)
    x0 += k1; x1 += ks2 + 4u;
    RND(13) RND(15) RND(26) RND(6)
    x0 += ks2; x1 += k0 + 5u;
#undef RND
    o0 = x0; o1 = x1;
}

// gumbel draw, jax_threefry_partitionable=True: bits = o0 ^ o1 of (key, (0, idx))
__device__ __forceinline__
float gumbel_at(uint32_t k0, uint32_t k1, uint32_t idx)
{
    uint32_t o0, o1;
    threefry2x32(k0, k1, 0u, idx, o0, o1);
    uint32_t bits = o0 ^ o1;
    uint32_t fb = (bits >> 9) | 0x3f800000u;
    float f = __uint_as_float(fb) - 1.0f;
    float u = fmaxf(f, 1.17549435e-38f);
    float l1 = (float)log((double)u);
    return -(float)log((double)(-l1));
}

// ---------------- K1: fused prep ---------------------------------------------
// blocks [0,4096): pe row + dtab reduction  (t = bid)
// blocks [4096,4352): gumbel draws
// blocks [4352,4356): cproj
// blocks [4356,4612): splitW
#define PREP_GUM   4096
#define PREP_CPROJ 4352
#define PREP_SPLITW 4356
#define PREP_TOTAL 4612

__global__ __launch_bounds__(256)
void prep_kernel(DivTab dt,
                 const float* __restrict__ W,      // W_embed [512,512]
                 const float* __restrict__ Wx,     // [512,2]
                 const float* __restrict__ bias,   // [512]
                 uint32_t ka0, uint32_t ka1, uint32_t kb0, uint32_t kb1)
{
    __shared__ float sh[32 * 33];     // splitW transpose OR pe row (512 floats)
    const int bid = blockIdx.x;
    const int tid = threadIdx.x;

    if (bid < PREP_GUM) {
        // ---- pe + dtab for token t ----
        const int t = bid;
        float tf = (float)t;
        float* spe = sh;
#pragma unroll
        for (int q = 0; q < 2; q++) {
            int n = tid + q * 256;
            float ang = tf * dt.v[n >> 1];
            float pv = (n & 1) ? cosf(ang) : sinf(ang);
            spe[n] = pv;
            g_pe[(size_t)t * 512 + n] = pv;
        }
        __syncthreads();
        if (tid < 32) {
            // identical Kahan order to the old dtab_kernel (lane-strided by 32)
            float s0 = 0.f, c0 = 0.f, s1 = 0.f, c1 = 0.f;
            for (int j = tid; j < 512; j += 32) {
                float e = bias[j] + spe[j];
                float p0 = e * Wx[2 * j];
                float p1 = e * Wx[2 * j + 1];
                float y0 = p0 - c0, t0 = s0 + y0; c0 = (t0 - s0) - y0; s0 = t0;
                float y1 = p1 - c1, t1 = s1 + y1; c1 = (t1 - s1) - y1; s1 = t1;
            }
            s0 += c0; s1 += c1;
#pragma unroll
            for (int off = 16; off; off >>= 1) {
                s0 += __shfl_xor_sync(0xffffffffu, s0, off);
                s1 += __shfl_xor_sync(0xffffffffu, s1, off);
            }
            if (tid == 0) {
                g_d[t * 2] = 8.0 * (double)s0;
                g_d[t * 2 + 1] = 8.0 * (double)s1;
            }
        }
    } else if (bid < PREP_CPROJ) {
        // ---- gumbel draws ----
        uint32_t idx = (uint32_t)(bid - PREP_GUM) * 256 + tid;   // 0..65535
        g_gum[0][idx] = gumbel_at(ka0, ka1, idx);
        g_gum[1][idx] = gumbel_at(kb0, kb1, idx);
    } else if (bid < PREP_SPLITW) {
        // ---- cproj: C = 8 * W_embed @ Wx (Kahan fp32) ----
        int idx = (bid - PREP_CPROJ) * 256 + tid;   // 0..1023
        int k = idx >> 1, i = idx & 1;
        float s = 0.f, c = 0.f;
        for (int j = 0; j < 512; j++) {
            float p = W[(size_t)k * 512 + j] * Wx[j * 2 + i];
            float y = p - c, t = s + y; c = (t - s) - y; s = t;
        }
        g_C[idx] = 8.0f * (s + c);
    } else {
        // ---- splitW: split + transpose W into bf16x2 [n][k] ----
        int q = bid - PREP_SPLITW;                  // 0..255
        int nt = (q & 15) * 32, kt = (q >> 4) * 32;
        int tx = tid & 31, ty = tid >> 5;           // 32 x 8
        for (int i = ty; i < 32; i += 8)
            sh[i * 33 + tx] = W[(size_t)(kt + i) * 512 + nt + tx];
        __syncthreads();
        for (int i = ty; i < 32; i += 8) {
            float x = sh[tx * 33 + i];   // = W[kt+tx][nt+i]
            __nv_bfloat16 h1 = __float2bfloat16(x);
            float r = x - __bfloat162float(h1);
            __nv_bfloat16 h2 = __float2bfloat16(r);
            size_t o = (size_t)(nt + i) * 512 + kt + tx;
            g_W1[o] = h1; g_W2[o] = h2;
        }
    }
}

// ---------------- K2: filter — logits from data directly, gumbel-max ---------
__global__ __launch_bounds__(256)
void filter_kernel(const float* __restrict__ data,
                   const float* __restrict__ Wv,   // [512,2]
                   const float* __restrict__ bf,   // [2]
                   const float* __restrict__ v0,   // [8,512]
                   const float* __restrict__ v1)   // [8,512]
{
    const int tid = threadIdx.x;
    const int b = blockIdx.x >> 9;            // 512 blocks per batch row
    __shared__ float sC[1024];
    __shared__ double cb[2][2];

    for (int k = tid; k < 1024; k += 256) sC[k] = g_C[k];

    if (tid < 32) {
        float s00 = 0, e00 = 0, s01 = 0, e01 = 0, s10 = 0, e10 = 0, s11 = 0, e11 = 0;
        for (int k = tid; k < 512; k += 32) {
            float w0 = Wv[2 * k], w1 = Wv[2 * k + 1];
            float a = v0[b * 512 + k], c = v1[b * 512 + k];
#define KA(s, e, p) { float y = (p) - e, t = s + y; e = (t - s) - y; s = t; }
            KA(s00, e00, a * w0) KA(s01, e01, a * w1)
            KA(s10, e10, c * w0) KA(s11, e11, c * w1)
#undef KA
        }
        s00 += e00; s01 += e01; s10 += e10; s11 += e11;
#pragma unroll
        for (int off = 16; off; off >>= 1) {
            s00 += __shfl_xor_sync(0xffffffffu, s00, off);
            s01 += __shfl_xor_sync(0xffffffffu, s01, off);
            s10 += __shfl_xor_sync(0xffffffffu, s10, off);
            s11 += __shfl_xor_sync(0xffffffffu, s11, off);
        }
        if (tid == 0) {
            cb[0][0] = (double)s00 + (double)bf[0]; cb[0][1] = (double)s01 + (double)bf[1];
            cb[1][0] = (double)s10 + (double)bf[0]; cb[1][1] = (double)s11 + (double)bf[1];
        }
    }
    __syncthreads();

    const int warp = tid >> 5, lane = tid & 31;
    const int m = blockIdx.x * 8 + warp;      // global token row
    const int tloc = m & 4095;
    const float4* dp = (const float4*)(data + (size_t)m * 512);

    float d0 = 0.f, c0 = 0.f, d1 = 0.f, c1 = 0.f;
#pragma unroll
    for (int r = 0; r < 4; r++) {
        int j4 = lane + 32 * r;
        float4 x = dp[j4];
        int j = j4 * 8;
        float p0 = x.x * sC[j + 0] + x.y * sC[j + 2] + x.z * sC[j + 4] + x.w * sC[j + 6];
        float p1 = x.x * sC[j + 1] + x.y * sC[j + 3] + x.z * sC[j + 5] + x.w * sC[j + 7];
        float y0 = p0 - c0, t0 = d0 + y0; c0 = (t0 - d0) - y0; d0 = t0;
        float y1 = p1 - c1, t1 = d1 + y1; c1 = (t1 - d1) - y1; d1 = t1;
    }
    d0 += c0; d1 += c1;
#pragma unroll
    for (int off = 16; off; off >>= 1) {
        d0 += __shfl_xor_sync(0xffffffffu, d0, off);
        d1 += __shfl_xor_sync(0xffffffffu, d1, off);
    }
    if (lane == 0) {
        double sd0 = g_d[tloc * 2], sd1 = g_d[tloc * 2 + 1];
        uint32_t base = (uint32_t)(b * 8192 + 2 * tloc);
        float g00 = g_gum[0][base],     g01 = g_gum[0][base + 1u];
        float g10 = g_gum[1][base],     g11 = g_gum[1][base + 1u];
        float l00 = (float)((double)d0 + sd0 + cb[0][0]);
        float l01 = (float)((double)d1 + sd1 + cb[0][1]);
        float l10 = (float)((double)d0 + sd0 + cb[1][0]);
        float l11 = (float)((double)d1 + sd1 + cb[1][1]);
        int f0 = ((l00 + g00) >= (l01 + g01));
        int f1 = ((l10 + g10) >= (l11 + g11));
        g_mask[m] = f0 & f1;
    }
}

// ---------------- K3: per-row stable exclusive scan --> sel indices ----------
__global__ __launch_bounds__(256)
void scan_kernel()
{
    const int b = blockIdx.x;
    const int tid = threadIdx.x;
    const int base = tid * 16;

    int m[16];
    int cnt = 0;
#pragma unroll
    for (int q = 0; q < 16; q++) {
        m[q] = g_mask[b * 4096 + base + q];
        cnt += m[q];
    }

    const int lane = tid & 31, warp = tid >> 5;
    int v = cnt;
#pragma unroll
    for (int off = 1; off < 32; off <<= 1) {
        int n2 = __shfl_up_sync(0xffffffffu, v, off);
        if (lane >= off) v += n2;
    }
    __shared__ int wtot[8];
    if (lane == 31) wtot[warp] = v;
    __syncthreads();
    int woff = 0;
    for (int w = 0; w < warp; w++) woff += wtot[w];
    int excl = woff + v - cnt;

    int pos = excl;
#pragma unroll
    for (int q = 0; q < 16; q++) {
        if (m[q]) g_sel[b * 4096 + pos++] = base + q;
    }
    if (tid == 255) g_lens[b] = excl + cnt;
}

// ---------------- K4: pack selected rows -> bf16x2 splits, or pad out --------
__global__ __launch_bounds__(256)
void packA_kernel(const float* __restrict__ data, float* __restrict__ out)
{
    const int tid = threadIdx.x;
    const int rl = tid >> 7;                 // 0..1 row within block
    const int c4 = tid & 127;                // float4 index in row
    const int p = blockIdx.x * 2 + rl;       // packed row 0..32767
    const int b = p >> 12, k = p & 4095;
    if (k >= g_lens[b]) {
        ((float4*)(out + (size_t)p * 512))[c4] = make_float4(0.f, 0.f, 0.f, 0.f);
        return;
    }
    const int t = g_sel[p];
    float4 v = ((const float4*)(data + ((size_t)(b << 12) + t) * 512))[c4];
    float x[4] = {v.x, v.y, v.z, v.w};
    __nv_bfloat16 h1[4], h2[4];
#pragma unroll
    for (int i = 0; i < 4; i++) {
        h1[i] = __float2bfloat16(x[i]);
        float r = x[i] - __bfloat162float(h1[i]);
        h2[i] = __float2bfloat16(r);
    }
    size_t o4 = (size_t)p * 128 + c4;
    uint2 u;
    __nv_bfloat162 pk;
#define PACK(dst, h) \
    pk = __halves2bfloat162((h)[0], (h)[1]); u.x = *(uint32_t*)&pk; \
    pk = __halves2bfloat162((h)[2], (h)[3]); u.y = *(uint32_t*)&pk; \
    ((uint2*)(dst))[o4] = u;
    PACK(g_A1, h1) PACK(g_A2, h2)
#undef PACK
}

// ---------------- K5: mma.sync bf16x2 GEMM over packed rows -> out -----------
// CTA 128x128, 512 thr (16 warps, warp tile 32x32), K chunks of 32, 3-stage.
// SMEM rows padded to 40 bf16 (80B) -> conflict-free ldmatrix, 16B aligned.
#define ROWB 80
#define MATB (128 * ROWB)          // 10240 B per matrix
#define STAGEB (4 * MATB)          // 40960 B per stage (A1,A2,W1,W2)
#define NSTAGE 3
#define GEMM_SMEM (NSTAGE * STAGEB)    // 122880 B

__global__ __launch_bounds__(512, 1)
void mma_gemm_kernel(const float* __restrict__ bias, float* __restrict__ out)
{
    const int n0 = blockIdx.x * 128;
    const int m0 = blockIdx.y * 128;
    const int len = g_lens[m0 >> 12];
    if ((m0 & 4095) >= len) return;          // whole m-block beyond packed length

    extern __shared__ char smem[];
    const uint32_t sb = smem_to_u32(smem);
    const int tid = threadIdx.x;
    const int lane = tid & 31;
    const int w = tid >> 5;
    const int wm = w & 3;          // 4 m-strips of 32
    const int wn = w >> 2;         // 4 n-strips of 32

    const __nv_bfloat16* gmat[4] = {g_A1, g_A2, g_W1, g_W2};

    auto issue_copy = [&](int ch, int st) {
        const int k0 = ch * 32;
#pragma unroll
        for (int it = 0; it < 4; it++) {
            int idx = tid + it * 512;           // 0..2047
            int mi = idx >> 9;                  // matrix 0..3
            int r  = (idx >> 2) & 127;          // row in tile
            int c  = idx & 3;                   // 16B chunk in row
            int grow = ((mi < 2) ? m0 : n0) + r;
            const __nv_bfloat16* gp = gmat[mi] + (size_t)grow * 512 + k0 + c * 8;
            cpasync16(sb + st * STAGEB + mi * MATB + r * ROWB + c * 16, gp);
        }
        asm volatile("cp.async.commit_group;" ::: "memory");
    };

    float facc[2][4][4];
#pragma unroll
    for (int a = 0; a < 2; a++)
#pragma unroll
        for (int b = 0; b < 4; b++)
#pragma unroll
            for (int c = 0; c < 4; c++) facc[a][b][c] = 0.f;

    issue_copy(0, 0);
    issue_copy(1, 1);

    const int rsel = lane & 15;
    const int chalf = (lane >> 4) << 4;     // 0 or 16 bytes

    for (int ch = 0; ch < 16; ch++) {
        const int st = ch % NSTAGE;
        asm volatile("cp.async.wait_group 1;" ::: "memory");
        __syncthreads();
        if (ch + 2 < 16) issue_copy(ch + 2, (ch + 2) % NSTAGE);

        const uint32_t bst = sb + st * STAGEB;
#pragma unroll
        for (int ks = 0; ks < 2; ks++) {
            const int colb = ks * 32 + chalf;
            uint32_t fa[2][2][4], fb[2][2][4];
#pragma unroll
            for (int sp = 0; sp < 2; sp++) {
#pragma unroll
                for (int mt = 0; mt < 2; mt++)
                    ldm_x4(fa[sp][mt],
                           bst + sp * MATB + (wm * 32 + mt * 16 + rsel) * ROWB + colb);
#pragma unroll
                for (int ng = 0; ng < 2; ng++)
                    ldm_x4(fb[sp][ng],
                           bst + (2 + sp) * MATB + (wn * 32 + ng * 16 + rsel) * ROWB + colb);
            }
            // products: A1*W1, A1*W2, A2*W1  (A2*W2 ~ 2^-18 rel, omitted)
            const int pa[3] = {0, 0, 1};
            const int pb[3] = {0, 1, 0};
#pragma unroll
            for (int p = 0; p < 3; p++)
#pragma unroll
                for (int mt = 0; mt < 2; mt++)
#pragma unroll
                    for (int ng = 0; ng < 2; ng++) {
                        mma16816(facc[mt][ng * 2 + 0], fa[pa[p]][mt],
                                 fb[pb[p]][ng][0], fb[pb[p]][ng][2]);
                        mma16816(facc[mt][ng * 2 + 1], fa[pa[p]][mt],
                                 fb[pb[p]][ng][1], fb[pb[p]][ng][3]);
                    }
        }
        __syncthreads();   // all reads of stage st done before it is re-issued
    }

    // epilogue: per packed row m -> token t = g_sel[m]; out[m] = (acc+b+pe[t])*8
    int rowm[4], rowt[4];
    bool rok[4];
#pragma unroll
    for (int q = 0; q < 4; q++) {
        int mt = q >> 1, hh = q & 1;
        int m = m0 + wm * 32 + mt * 16 + (lane >> 2) + hh * 8;
        int k = m & 4095;
        rowm[q] = m;
        rok[q] = (k < len);
        rowt[q] = rok[q] ? g_sel[m] : 0;
    }

#pragma unroll
    for (int mt = 0; mt < 2; mt++)
#pragma unroll
        for (int nt = 0; nt < 4; nt++) {
            int n = n0 + wn * 32 + nt * 8 + (lane & 3) * 2;
            float b0 = bias[n], b1 = bias[n + 1];
            {
                int q = mt * 2;
                if (rok[q]) {
                    const float* pe = g_pe + (size_t)rowt[q] * 512 + n;
                    float2 v;
                    v.x = (facc[mt][nt][0] + b0 + pe[0]) * 8.0f;
                    v.y = (facc[mt][nt][1] + b1 + pe[1]) * 8.0f;
                    *(float2*)(out + (size_t)rowm[q] * 512 + n) = v;
                }
            }
            {
                int q = mt * 2 + 1;
                if (rok[q]) {
                    const float* pe = g_pe + (size_t)rowt[q] * 512 + n;
                    float2 v;
                    v.x = (facc[mt][nt][2] + b0 + pe[0]) * 8.0f;
                    v.y = (facc[mt][nt][3] + b1 + pe[1]) * 8.0f;
                    *(float2*)(out + (size_t)rowm[q] * 512 + n) = v;
                }
            }
        }
}

// ---------------- launch ------------------------------------------------------
extern "C" void kernel_launch(void* const* d_in, const int* in_sizes, int n_in,
                              void* d_out, int out_size)
{
    const float* data    = (const float*)d_in[0];
    const float* v0      = (const float*)d_in[1];
    const float* v1      = (const float*)d_in[2];
    const float* W_embed = (const float*)d_in[3];
    const float* b_embed = (const float*)d_in[4];
    const float* Wx      = (const float*)d_in[5];
    const float* Wv      = (const float*)d_in[6];
    const float* b_f     = (const float*)d_in[7];
    float* out = (float*)d_out;

    uint32_t ka0, ka1, kb0, kb1;
    threefry2x32(0u, 42u, 0u, 0u, ka0, ka1);
    threefry2x32(0u, 42u, 0u, 1u, kb0, kb1);

    // host-computed inv-freq table (identical IEEE double exp/log chain)
    DivTab dt;
    {
        double c = -log(10000.0) / 512.0;
        for (int j = 0; j < 256; j++) {
            float arg = (float)(2 * j) * (float)c;
            dt.v[j] = (float)exp((double)arg);
        }
    }

    cudaFuncSetAttribute(mma_gemm_kernel,
                         cudaFuncAttributeMaxDynamicSharedMemorySize, GEMM_SMEM);

    prep_kernel<<<PREP_TOTAL, 256>>>(dt, W_embed, Wx, b_embed, ka0, ka1, kb0, kb1);
    filter_kernel<<<4096, 256>>>(data, Wv, b_f, v0, v1);
    scan_kernel<<<8, 256>>>();
    packA_kernel<<<16384, 256>>>(data, out);
    mma_gemm_kernel<<<dim3(4, 256), 512, GEMM_SMEM>>>(b_embed, out);
}

// round 17
// speedup vs baseline: 4.7629x; 1.0189x over previous
#include <cuda_runtime.h>
#include <cuda_bf16.h>
#include <cstdint>
#include <math.h>

// Problem constants
#define BB 8
#define TT 4096
#define HH 512
#define MTOT (BB*TT)          // 32768 rows

struct DivTab { float v[256]; };   // host-computed inv-freq table (1KB by-value)

// ---------------- scratch (static device globals; no allocation) -------------
__device__ __align__(16) float g_pe[(size_t)TT * HH];      // 8 MB
__device__ float  g_C[HH * 2];       // 8 * W_embed @ Wx  (fp32, Kahan-computed)
__device__ double g_d[TT * 2];       // 8 * (b_embed + pe[t]) @ Wx
__device__ __align__(16) float g_gum[2][65536];  // precomputed gumbel draws
__device__ int    g_mask[MTOT];
__device__ int    g_sel[MTOT];
__device__ int    g_lens[BB];
__device__ __align__(16) __nv_bfloat16 g_A1[(size_t)MTOT * HH];  // packed rows only
__device__ __align__(16) __nv_bfloat16 g_A2[(size_t)MTOT * HH];
__device__ __align__(16) __nv_bfloat16 g_W1[HH * HH];            // transposed [n][k]
__device__ __align__(16) __nv_bfloat16 g_W2[HH * HH];

// ---------------- helpers ----------------------------------------------------
__device__ __forceinline__ uint32_t smem_to_u32(const void* p) {
    uint32_t a;
    asm("{ .reg .u64 t; cvta.to.shared.u64 t, %1; cvt.u32.u64 %0, t; }" : "=r"(a) : "l"(p));
    return a;
}
__device__ __forceinline__ void cpasync16(uint32_t sa, const void* g) {
    asm volatile("cp.async.cg.shared.global [%0], [%1], 16;" :: "r"(sa), "l"(g));
}
__device__ __forceinline__ void ldm_x4(uint32_t* r, uint32_t addr) {
    asm volatile("ldmatrix.sync.aligned.m8n8.x4.shared.b16 {%0,%1,%2,%3}, [%4];"
        : "=r"(r[0]), "=r"(r[1]), "=r"(r[2]), "=r"(r[3]) : "r"(addr));
}
__device__ __forceinline__ void mma16816(float* d, const uint32_t* a,
                                         uint32_t b0, uint32_t b1) {
    asm volatile("mma.sync.aligned.m16n8k16.row.col.f32.bf16.bf16.f32 "
        "{%0,%1,%2,%3}, {%4,%5,%6,%7}, {%8,%9}, {%0,%1,%2,%3};"
        : "+f"(d[0]), "+f"(d[1]), "+f"(d[2]), "+f"(d[3])
        : "r"(a[0]), "r"(a[1]), "r"(a[2]), "r"(a[3]), "r"(b0), "r"(b1));
}

// ---------------- threefry2x32 (Random123 / JAX-compatible) ------------------
__host__ __device__ __forceinline__
void threefry2x32(uint32_t k0, uint32_t k1, uint32_t x0, uint32_t x1,
                  uint32_t& o0, uint32_t& o1)
{
    uint32_t ks2 = k0 ^ k1 ^ 0x1BD11BDAu;
    x0 += k0; x1 += k1;
#define RND(r) { x0 += x1; x1 = (x1 << r) | (x1 >> (32 - r)); x1 ^= x0; }
    RND(13) RND(15) RND(26) RND(6)
    x0 += k1; x1 += ks2 + 1u;
    RND(17) RND(29) RND(16) RND(24)
    x0 += ks2; x1 += k0 + 2u;
    RND(13) RND(15) RND(26) RND(6)
    x0 += k0; x1 += k1 + 3u;
    RND(17) RND(29) RND(16) RND(24)
    x0 += k1; x1 += ks2 + 4u;
    RND(13) RND(15) RND(26) RND(6)
    x0 += ks2; x1 += k0 + 5u;
#undef RND
    o0 = x0; o1 = x1;
}

// gumbel draw, jax_threefry_partitionable=True: bits = o0 ^ o1 of (key, (0, idx))
__device__ __forceinline__
float gumbel_at(uint32_t k0, uint32_t k1, uint32_t idx)
{
    uint32_t o0, o1;
    threefry2x32(k0, k1, 0u, idx, o0, o1);
    uint32_t bits = o0 ^ o1;
    uint32_t fb = (bits >> 9) | 0x3f800000u;
    float f = __uint_as_float(fb) - 1.0f;
    float u = fmaxf(f, 1.17549435e-38f);
    float l1 = (float)log((double)u);
    return -(float)log((double)(-l1));
}

// ---------------- K1: fused prep ---------------------------------------------
#define PREP_GUM   4096
#define PREP_CPROJ 4352
#define PREP_SPLITW 4356
#define PREP_TOTAL 4612

__global__ __launch_bounds__(256)
void prep_kernel(DivTab dt,
                 const float* __restrict__ W,      // W_embed [512,512]
                 const float* __restrict__ Wx,     // [512,2]
                 const float* __restrict__ bias,   // [512]
                 uint32_t ka0, uint32_t ka1, uint32_t kb0, uint32_t kb1)
{
    __shared__ float sh[32 * 33];
    const int bid = blockIdx.x;
    const int tid = threadIdx.x;

    if (bid < PREP_GUM) {
        // ---- pe + dtab for token t ----
        const int t = bid;
        float tf = (float)t;
        float* spe = sh;
#pragma unroll
        for (int q = 0; q < 2; q++) {
            int n = tid + q * 256;
            float ang = tf * dt.v[n >> 1];
            float pv = (n & 1) ? cosf(ang) : sinf(ang);
            spe[n] = pv;
            g_pe[(size_t)t * 512 + n] = pv;
        }
        __syncthreads();
        if (tid < 32) {
            float s0 = 0.f, c0 = 0.f, s1 = 0.f, c1 = 0.f;
            for (int j = tid; j < 512; j += 32) {
                float e = bias[j] + spe[j];
                float p0 = e * Wx[2 * j];
                float p1 = e * Wx[2 * j + 1];
                float y0 = p0 - c0, t0 = s0 + y0; c0 = (t0 - s0) - y0; s0 = t0;
                float y1 = p1 - c1, t1 = s1 + y1; c1 = (t1 - s1) - y1; s1 = t1;
            }
            s0 += c0; s1 += c1;
#pragma unroll
            for (int off = 16; off; off >>= 1) {
                s0 += __shfl_xor_sync(0xffffffffu, s0, off);
                s1 += __shfl_xor_sync(0xffffffffu, s1, off);
            }
            if (tid == 0) {
                g_d[t * 2] = 8.0 * (double)s0;
                g_d[t * 2 + 1] = 8.0 * (double)s1;
            }
        }
    } else if (bid < PREP_CPROJ) {
        uint32_t idx = (uint32_t)(bid - PREP_GUM) * 256 + tid;   // 0..65535
        g_gum[0][idx] = gumbel_at(ka0, ka1, idx);
        g_gum[1][idx] = gumbel_at(kb0, kb1, idx);
    } else if (bid < PREP_SPLITW) {
        int idx = (bid - PREP_CPROJ) * 256 + tid;   // 0..1023
        int k = idx >> 1, i = idx & 1;
        float s = 0.f, c = 0.f;
        for (int j = 0; j < 512; j++) {
            float p = W[(size_t)k * 512 + j] * Wx[j * 2 + i];
            float y = p - c, t = s + y; c = (t - s) - y; s = t;
        }
        g_C[idx] = 8.0f * (s + c);
    } else {
        int q = bid - PREP_SPLITW;                  // 0..255
        int nt = (q & 15) * 32, kt = (q >> 4) * 32;
        int tx = tid & 31, ty = tid >> 5;           // 32 x 8
        for (int i = ty; i < 32; i += 8)
            sh[i * 33 + tx] = W[(size_t)(kt + i) * 512 + nt + tx];
        __syncthreads();
        for (int i = ty; i < 32; i += 8) {
            float x = sh[tx * 33 + i];   // = W[kt+tx][nt+i]
            __nv_bfloat16 h1 = __float2bfloat16(x);
            float r = x - __bfloat162float(h1);
            __nv_bfloat16 h2 = __float2bfloat16(r);
            size_t o = (size_t)(nt + i) * 512 + kt + tx;
            g_W1[o] = h1; g_W2[o] = h2;
        }
    }
}

// ---------------- K2: filter — 2 tokens per warp, gumbel-max -----------------
__global__ __launch_bounds__(256)
void filter_kernel(const float* __restrict__ data,
                   const float* __restrict__ Wv,   // [512,2]
                   const float* __restrict__ bf,   // [2]
                   const float* __restrict__ v0,   // [8,512]
                   const float* __restrict__ v1)   // [8,512]
{
    const int tid = threadIdx.x;
    const int b = blockIdx.x >> 8;            // 256 blocks per batch row
    __shared__ float sC[1024];
    __shared__ double cb[2][2];

    for (int k = tid; k < 1024; k += 256) sC[k] = g_C[k];

    if (tid < 32) {
        float s00 = 0, e00 = 0, s01 = 0, e01 = 0, s10 = 0, e10 = 0, s11 = 0, e11 = 0;
        for (int k = tid; k < 512; k += 32) {
            float w0 = Wv[2 * k], w1 = Wv[2 * k + 1];
            float a = v0[b * 512 + k], c = v1[b * 512 + k];
#define KA(s, e, p) { float y = (p) - e, t = s + y; e = (t - s) - y; s = t; }
            KA(s00, e00, a * w0) KA(s01, e01, a * w1)
            KA(s10, e10, c * w0) KA(s11, e11, c * w1)
#undef KA
        }
        s00 += e00; s01 += e01; s10 += e10; s11 += e11;
#pragma unroll
        for (int off = 16; off; off >>= 1) {
            s00 += __shfl_xor_sync(0xffffffffu, s00, off);
            s01 += __shfl_xor_sync(0xffffffffu, s01, off);
            s10 += __shfl_xor_sync(0xffffffffu, s10, off);
            s11 += __shfl_xor_sync(0xffffffffu, s11, off);
        }
        if (tid == 0) {
            cb[0][0] = (double)s00 + (double)bf[0]; cb[0][1] = (double)s01 + (double)bf[1];
            cb[1][0] = (double)s10 + (double)bf[0]; cb[1][1] = (double)s11 + (double)bf[1];
        }
    }
    __syncthreads();

    const int warp = tid >> 5, lane = tid & 31;
    const int m0 = blockIdx.x * 16 + warp * 2;    // two tokens per warp
    const float4* dpA = (const float4*)(data + (size_t)m0 * 512);
    const float4* dpB = (const float4*)(data + (size_t)(m0 + 1) * 512);

    // two independent Kahan chains, identical per-token op order
    float dA0 = 0.f, cA0 = 0.f, dA1 = 0.f, cA1 = 0.f;
    float dB0 = 0.f, cB0 = 0.f, dB1 = 0.f, cB1 = 0.f;
#pragma unroll
    for (int r = 0; r < 4; r++) {
        int j4 = lane + 32 * r;
        float4 xA = dpA[j4];
        float4 xB = dpB[j4];
        int j = j4 * 8;
        float w0a = sC[j + 0], w1a = sC[j + 1], w0b = sC[j + 2], w1b = sC[j + 3];
        float w0c = sC[j + 4], w1c = sC[j + 5], w0d = sC[j + 6], w1d = sC[j + 7];
        float pA0 = xA.x * w0a + xA.y * w0b + xA.z * w0c + xA.w * w0d;
        float pA1 = xA.x * w1a + xA.y * w1b + xA.z * w1c + xA.w * w1d;
        float pB0 = xB.x * w0a + xB.y * w0b + xB.z * w0c + xB.w * w0d;
        float pB1 = xB.x * w1a + xB.y * w1b + xB.z * w1c + xB.w * w1d;
        float y, t;
        y = pA0 - cA0; t = dA0 + y; cA0 = (t - dA0) - y; dA0 = t;
        y = pA1 - cA1; t = dA1 + y; cA1 = (t - dA1) - y; dA1 = t;
        y = pB0 - cB0; t = dB0 + y; cB0 = (t - dB0) - y; dB0 = t;
        y = pB1 - cB1; t = dB1 + y; cB1 = (t - dB1) - y; dB1 = t;
    }
    dA0 += cA0; dA1 += cA1; dB0 += cB0; dB1 += cB1;
#pragma unroll
    for (int off = 16; off; off >>= 1) {
        dA0 += __shfl_xor_sync(0xffffffffu, dA0, off);
        dA1 += __shfl_xor_sync(0xffffffffu, dA1, off);
        dB0 += __shfl_xor_sync(0xffffffffu, dB0, off);
        dB1 += __shfl_xor_sync(0xffffffffu, dB1, off);
    }
    if (lane == 0) {
#pragma unroll
        for (int q = 0; q < 2; q++) {
            int m = m0 + q;
            int tloc = m & 4095;
            float d0 = q ? dB0 : dA0;
            float d1 = q ? dB1 : dA1;
            double sd0 = g_d[tloc * 2], sd1 = g_d[tloc * 2 + 1];
            uint32_t base = (uint32_t)(b * 8192 + 2 * tloc);
            float g00 = g_gum[0][base], g01 = g_gum[0][base + 1u];
            float g10 = g_gum[1][base], g11 = g_gum[1][base + 1u];
            float l00 = (float)((double)d0 + sd0 + cb[0][0]);
            float l01 = (float)((double)d1 + sd1 + cb[0][1]);
            float l10 = (float)((double)d0 + sd0 + cb[1][0]);
            float l11 = (float)((double)d1 + sd1 + cb[1][1]);
            int f0 = ((l00 + g00) >= (l01 + g01));
            int f1 = ((l10 + g10) >= (l11 + g11));
            g_mask[m] = f0 & f1;
        }
    }
}

// ---------------- K3: per-row stable exclusive scan --> sel indices ----------
__global__ __launch_bounds__(256)
void scan_kernel()
{
    const int b = blockIdx.x;
    const int tid = threadIdx.x;
    const int base = tid * 16;

    int m[16];
    int cnt = 0;
#pragma unroll
    for (int q = 0; q < 16; q++) {
        m[q] = g_mask[b * 4096 + base + q];
        cnt += m[q];
    }

    const int lane = tid & 31, warp = tid >> 5;
    int v = cnt;
#pragma unroll
    for (int off = 1; off < 32; off <<= 1) {
        int n2 = __shfl_up_sync(0xffffffffu, v, off);
        if (lane >= off) v += n2;
    }
    __shared__ int wtot[8];
    if (lane == 31) wtot[warp] = v;
    __syncthreads();
    int woff = 0;
    for (int w = 0; w < warp; w++) woff += wtot[w];
    int excl = woff + v - cnt;

    int pos = excl;
#pragma unroll
    for (int q = 0; q < 16; q++) {
        if (m[q]) g_sel[b * 4096 + pos++] = base + q;
    }
    if (tid == 255) g_lens[b] = excl + cnt;
}

// ---------------- K4: pack selected rows -> bf16x2 splits --------------------
__global__ __launch_bounds__(256)
void packA_kernel(const float* __restrict__ data)
{
    const int tid = threadIdx.x;
    const int rl = tid >> 7;                 // 0..1 row within block
    const int c4 = tid & 127;                // float4 index in row
    const int p = blockIdx.x * 2 + rl;       // packed row 0..32767
    const int b = p >> 12, k = p & 4095;
    if (k >= g_lens[b]) return;              // padding handled by gemm
    const int t = g_sel[p];
    float4 v = ((const float4*)(data + ((size_t)(b << 12) + t) * 512))[c4];
    float x[4] = {v.x, v.y, v.z, v.w};
    __nv_bfloat16 h1[4], h2[4];
#pragma unroll
    for (int i = 0; i < 4; i++) {
        h1[i] = __float2bfloat16(x[i]);
        float r = x[i] - __bfloat162float(h1[i]);
        h2[i] = __float2bfloat16(r);
    }
    size_t o4 = (size_t)p * 128 + c4;
    uint2 u;
    __nv_bfloat162 pk;
#define PACK(dst, h) \
    pk = __halves2bfloat162((h)[0], (h)[1]); u.x = *(uint32_t*)&pk; \
    pk = __halves2bfloat162((h)[2], (h)[3]); u.y = *(uint32_t*)&pk; \
    ((uint2*)(dst))[o4] = u;
    PACK(g_A1, h1) PACK(g_A2, h2)
#undef PACK
}

// ---------------- K5: mma.sync bf16x2 GEMM over packed rows -> out -----------
// CTA 128x128, 512 thr (16 warps, warp tile 32x32), K chunks of 32, 3-stage.
// Inactive/padded regions of out are zero-filled here (out poisoned by harness).
#define ROWB 80
#define MATB (128 * ROWB)          // 10240 B per matrix
#define STAGEB (4 * MATB)          // 40960 B per stage (A1,A2,W1,W2)
#define NSTAGE 3
#define GEMM_SMEM (NSTAGE * STAGEB)    // 122880 B

__global__ __launch_bounds__(512, 1)
void mma_gemm_kernel(const float* __restrict__ bias, float* __restrict__ out)
{
    const int n0 = blockIdx.x * 128;
    const int m0 = blockIdx.y * 128;
    const int len = g_lens[m0 >> 12];
    const int tid = threadIdx.x;

    if ((m0 & 4095) >= len) {
        // fully padded tile: write zeros for this 128x128 block of out
        float4 z = make_float4(0.f, 0.f, 0.f, 0.f);
#pragma unroll
        for (int q = 0; q < 8; q++) {
            int idx = tid + q * 512;             // 0..4095 float4s
            int r = idx >> 5, c4 = idx & 31;
            ((float4*)(out + (size_t)(m0 + r) * 512 + n0))[c4] = z;
        }
        return;
    }

    extern __shared__ char smem[];
    const uint32_t sb = smem_to_u32(smem);
    const int lane = tid & 31;
    const int w = tid >> 5;
    const int wm = w & 3;          // 4 m-strips of 32
    const int wn = w >> 2;         // 4 n-strips of 32

    const __nv_bfloat16* gmat[4] = {g_A1, g_A2, g_W1, g_W2};

    auto issue_copy = [&](int ch, int st) {
        const int k0 = ch * 32;
#pragma unroll
        for (int it = 0; it < 4; it++) {
            int idx = tid + it * 512;           // 0..2047
            int mi = idx >> 9;                  // matrix 0..3
            int r  = (idx >> 2) & 127;          // row in tile
            int c  = idx & 3;                   // 16B chunk in row
            int grow = ((mi < 2) ? m0 : n0) + r;
            const __nv_bfloat16* gp = gmat[mi] + (size_t)grow * 512 + k0 + c * 8;
            cpasync16(sb + st * STAGEB + mi * MATB + r * ROWB + c * 16, gp);
        }
        asm volatile("cp.async.commit_group;" ::: "memory");
    };

    float facc[2][4][4];
#pragma unroll
    for (int a = 0; a < 2; a++)
#pragma unroll
        for (int b = 0; b < 4; b++)
#pragma unroll
            for (int c = 0; c < 4; c++) facc[a][b][c] = 0.f;

    issue_copy(0, 0);
    issue_copy(1, 1);

    const int rsel = lane & 15;
    const int chalf = (lane >> 4) << 4;     // 0 or 16 bytes

    for (int ch = 0; ch < 16; ch++) {
        const int st = ch % NSTAGE;
        asm volatile("cp.async.wait_group 1;" ::: "memory");
        __syncthreads();
        if (ch + 2 < 16) issue_copy(ch + 2, (ch + 2) % NSTAGE);

        const uint32_t bst = sb + st * STAGEB;
#pragma unroll
        for (int ks = 0; ks < 2; ks++) {
            const int colb = ks * 32 + chalf;
            uint32_t fa[2][2][4], fb[2][2][4];
#pragma unroll
            for (int sp = 0; sp < 2; sp++) {
#pragma unroll
                for (int mt = 0; mt < 2; mt++)
                    ldm_x4(fa[sp][mt],
                           bst + sp * MATB + (wm * 32 + mt * 16 + rsel) * ROWB + colb);
#pragma unroll
                for (int ng = 0; ng < 2; ng++)
                    ldm_x4(fb[sp][ng],
                           bst + (2 + sp) * MATB + (wn * 32 + ng * 16 + rsel) * ROWB + colb);
            }
            // products: A1*W1, A1*W2, A2*W1  (A2*W2 ~ 2^-18 rel, omitted)
            const int pa[3] = {0, 0, 1};
            const int pb[3] = {0, 1, 0};
#pragma unroll
            for (int p = 0; p < 3; p++)
#pragma unroll
                for (int mt = 0; mt < 2; mt++)
#pragma unroll
                    for (int ng = 0; ng < 2; ng++) {
                        mma16816(facc[mt][ng * 2 + 0], fa[pa[p]][mt],
                                 fb[pb[p]][ng][0], fb[pb[p]][ng][2]);
                        mma16816(facc[mt][ng * 2 + 1], fa[pa[p]][mt],
                                 fb[pb[p]][ng][1], fb[pb[p]][ng][3]);
                    }
        }
        __syncthreads();   // all reads of stage st done before it is re-issued
    }

    // epilogue: row m -> token t = g_sel[m]; out[m] = (acc+b+pe[t])*8 or zero
    int rowm[4], rowt[4];
    bool rok[4];
#pragma unroll
    for (int q = 0; q < 4; q++) {
        int mt = q >> 1, hh = q & 1;
        int m = m0 + wm * 32 + mt * 16 + (lane >> 2) + hh * 8;
        int k = m & 4095;
        rowm[q] = m;
        rok[q] = (k < len);
        rowt[q] = rok[q] ? g_sel[m] : 0;
    }

#pragma unroll
    for (int mt = 0; mt < 2; mt++)
#pragma unroll
        for (int nt = 0; nt < 4; nt++) {
            int n = n0 + wn * 32 + nt * 8 + (lane & 3) * 2;
            float b0 = bias[n], b1 = bias[n + 1];
#pragma unroll
            for (int hh = 0; hh < 2; hh++) {
                int q = mt * 2 + hh;
                float2 v;
                if (rok[q]) {
                    const float* pe = g_pe + (size_t)rowt[q] * 512 + n;
                    v.x = (facc[mt][nt][hh * 2 + 0] + b0 + pe[0]) * 8.0f;
                    v.y = (facc[mt][nt][hh * 2 + 1] + b1 + pe[1]) * 8.0f;
                } else {
                    v.x = 0.f; v.y = 0.f;
                }
                *(float2*)(out + (size_t)rowm[q] * 512 + n) = v;
            }
        }
}

// ---------------- launch ------------------------------------------------------
extern "C" void kernel_launch(void* const* d_in, const int* in_sizes, int n_in,
                              void* d_out, int out_size)
{
    const float* data    = (const float*)d_in[0];
    const float* v0      = (const float*)d_in[1];
    const float* v1      = (const float*)d_in[2];
    const float* W_embed = (const float*)d_in[3];
    const float* b_embed = (const float*)d_in[4];
    const float* Wx      = (const float*)d_in[5];
    const float* Wv      = (const float*)d_in[6];
    const float* b_f     = (const float*)d_in[7];
    float* out = (float*)d_out;

    uint32_t ka0, ka1, kb0, kb1;
    threefry2x32(0u, 42u, 0u, 0u, ka0, ka1);
    threefry2x32(0u, 42u, 0u, 1u, kb0, kb1);

    // host-computed inv-freq table (identical IEEE double exp/log chain)
    DivTab dt;
    {
        double c = -log(10000.0) / 512.0;
        for (int j = 0; j < 256; j++) {
            float arg = (float)(2 * j) * (float)c;
            dt.v[j] = (float)exp((double)arg);
        }
    }

    cudaFuncSetAttribute(mma_gemm_kernel,
                         cudaFuncAttributeMaxDynamicSharedMemorySize, GEMM_SMEM);

    prep_kernel<<<PREP_TOTAL, 256>>>(dt, W_embed, Wx, b_embed, ka0, ka1, kb0, kb1);
    filter_kernel<<<2048, 256>>>(data, Wv, b_f, v0, v1);
    scan_kernel<<<8, 256>>>();
    packA_kernel<<<16384, 256>>>(data);
    mma_gemm_kernel<<<dim3(4, 256), 512, GEMM_SMEM>>>(b_embed, out);
}